// round 9
// baseline (speedup 1.0000x reference)
#include <cuda_runtime.h>
#include <cuda_bf16.h>
#include <math.h>
#include <stdint.h>

// Problem constants
#define B_   4
#define S_   2048
#define D_   1024
#define H_   16
#define DK   64
#define MSEQ 2048
#define M_   (B_ * S_)   // 8192

// ---------------------------------------------------------------------------
// Scratch (__device__ globals; no allocations allowed)
// ---------------------------------------------------------------------------
__device__ float g_cos[MSEQ * (DK / 2)];
__device__ float g_sin[MSEQ * (DK / 2)];

__device__ __align__(16) __nv_bfloat16 g_xh[M_ * D_];
__device__ __align__(16) __nv_bfloat16 g_xl[M_ * D_];
__device__ __align__(16) __nv_bfloat16 g_ath[M_ * D_];
__device__ __align__(16) __nv_bfloat16 g_atl[M_ * D_];
__device__ __align__(16) __nv_bfloat16 g_qbh[M_ * D_];
__device__ __align__(16) __nv_bfloat16 g_qbl[M_ * D_];
__device__ __align__(16) __nv_bfloat16 g_kbh[M_ * D_];
__device__ __align__(16) __nv_bfloat16 g_kbl[M_ * D_];
__device__ __align__(16) __nv_bfloat16 g_vbh[M_ * D_];
__device__ __align__(16) __nv_bfloat16 g_vbl[M_ * D_];
__device__ __align__(16) __nv_bfloat16 g_wqh[D_ * D_];
__device__ __align__(16) __nv_bfloat16 g_wql[D_ * D_];
__device__ __align__(16) __nv_bfloat16 g_wkh[D_ * D_];
__device__ __align__(16) __nv_bfloat16 g_wkl[D_ * D_];
__device__ __align__(16) __nv_bfloat16 g_wvh[D_ * D_];
__device__ __align__(16) __nv_bfloat16 g_wvl[D_ * D_];
__device__ __align__(16) __nv_bfloat16 g_woh[D_ * D_];
__device__ __align__(16) __nv_bfloat16 g_wol[D_ * D_];

// ---------------------------------------------------------------------------
// PTX helpers (sm_80+ only; harness compiles for plain sm_103 — no tcgen05)
// ---------------------------------------------------------------------------
__device__ __forceinline__ uint32_t smem_to_u32(const void* p) {
    uint32_t a;
    asm("{ .reg .u64 t; cvta.to.shared.u64 t, %1; cvt.u32.u64 %0, t; }"
        : "=r"(a) : "l"(p));
    return a;
}
#define CP_ASYNC16(dst_u32, src_ptr) \
    asm volatile("cp.async.cg.shared.global [%0], [%1], 16;" \
                 :: "r"(dst_u32), "l"(src_ptr))
#define CP_COMMIT() asm volatile("cp.async.commit_group;" ::: "memory")
#define CP_WAIT(n) asm volatile("cp.async.wait_group %0;" :: "n"(n) : "memory")
#define LDMATRIX_X4(r0, r1, r2, r3, addr) \
    asm volatile("ldmatrix.sync.aligned.m8n8.x4.shared.b16 {%0,%1,%2,%3}, [%4];" \
                 : "=r"(r0), "=r"(r1), "=r"(r2), "=r"(r3) : "r"(addr))
#define LDMATRIX_X4_T(r0, r1, r2, r3, addr) \
    asm volatile("ldmatrix.sync.aligned.m8n8.x4.trans.shared.b16 {%0,%1,%2,%3}, [%4];" \
                 : "=r"(r0), "=r"(r1), "=r"(r2), "=r"(r3) : "r"(addr))
#define MMA_BF16(c, a, b0, b1) \
    asm volatile("mma.sync.aligned.m16n8k16.row.col.f32.bf16.bf16.f32 " \
                 "{%0,%1,%2,%3}, {%4,%5,%6,%7}, {%8,%9}, {%0,%1,%2,%3};" \
                 : "+f"((c)[0]), "+f"((c)[1]), "+f"((c)[2]), "+f"((c)[3]) \
                 : "r"((a)[0]), "r"((a)[1]), "r"((a)[2]), "r"((a)[3]), \
                   "r"(b0), "r"(b1))

__device__ __forceinline__ uint32_t pack_bf16x2(float lo, float hi) {
    uint32_t r;
    asm("cvt.rn.bf16x2.f32 %0, %1, %2;" : "=r"(r) : "f"(hi), "f"(lo));
    return r;
}
__device__ __forceinline__ void split_pack(float v0, float v1,
                                           uint32_t& rh, uint32_t& rl) {
    rh = pack_bf16x2(v0, v1);
    float h0 = __uint_as_float(rh << 16);
    float h1 = __uint_as_float(rh & 0xffff0000u);
    rl = pack_bf16x2(v0 - h0, v1 - h1);
}

// fast exp2, FFMA-only (no MUFU). |err| ~ 2e-6 relative.
__device__ __forceinline__ float exp2f_fast(float x) {
    x = fmaxf(x, -120.f);
    float z = __fadd_rn(x, 12582912.f);
    int ei = __float_as_int(z) - 0x4B400000;
    float f = x - __fadd_rn(z, -12582912.f);
    float p = 0.0013333558f;
    p = fmaf(p, f, 0.0096181291f);
    p = fmaf(p, f, 0.0555041087f);
    p = fmaf(p, f, 0.2402265070f);
    p = fmaf(p, f, 0.69314718056f);
    p = fmaf(p, f, 1.0f);
    return __int_as_float(__float_as_int(p) + (ei << 23));
}

__device__ __forceinline__ int get_pos(const int* __restrict__ tp32, int s) {
    return (tp32[1] == 0) ? tp32[2 * s] : tp32[s];
}

// ---------------------------------------------------------------------------
// split x (fp32 -> bf16 hi/lo) + RoPE tables folded in
// ---------------------------------------------------------------------------
__global__ void split_kernel(const float* __restrict__ in,
                             __nv_bfloat16* __restrict__ hi,
                             __nv_bfloat16* __restrict__ lo, int n)
{
    int i = blockIdx.x * blockDim.x + threadIdx.x;
    if (i < MSEQ * (DK / 2)) {
        int pos = i >> 5;
        int j   = i & 31;
        double freq = pow(10000.0, -(double)(2 * j) / (double)DK);
        double ang  = (double)pos * freq;
        g_cos[i] = (float)cos(ang);
        g_sin[i] = (float)sin(ang);
    }
    if (i < n) {
        float v = in[i];
        __nv_bfloat16 h = __float2bfloat16(v);
        hi[i] = h;
        lo[i] = __float2bfloat16(v - __bfloat162float(h));
    }
}

// ---------------------------------------------------------------------------
// Weight transpose + split: W[K][N] fp32 -> th/tl[N][K] bf16
// ---------------------------------------------------------------------------
__global__ void wsplit_kernel(const float* __restrict__ W,
                              __nv_bfloat16* __restrict__ th,
                              __nv_bfloat16* __restrict__ tl)
{
    __shared__ float t[32][33];
    int bx = blockIdx.x * 32;
    int by = blockIdx.y * 32;
    int tx = threadIdx.x, ty = threadIdx.y;
    for (int i = ty; i < 32; i += 8)
        t[i][tx] = W[(size_t)(by + i) * D_ + bx + tx];
    __syncthreads();
    for (int i = ty; i < 32; i += 8) {
        float v = t[tx][i];
        __nv_bfloat16 h = __float2bfloat16(v);
        size_t o = (size_t)(bx + i) * D_ + by + tx;
        th[o] = h;
        tl[o] = __float2bfloat16(v - __bfloat162float(h));
    }
}

// ---------------------------------------------------------------------------
// HMMA GEMM core: 3-stage circular buffer, ONE __syncthreads per K-chunk.
// ---------------------------------------------------------------------------
#define KCH      32
#define ROW_STR  80
#define TILE_B   (128 * ROW_STR)
#define STAGE_B  (4 * TILE_B)            // 40960: Ah, Al, Bh, Bl
#define GEMM_SMEM (3 * STAGE_B)          // 122880

__device__ __forceinline__ void gemm_core(
    const __nv_bfloat16* __restrict__ Ah, const __nv_bfloat16* __restrict__ Al,
    const __nv_bfloat16* __restrict__ Bh, const __nv_bfloat16* __restrict__ Bl,
    int m0, int n0, char* smem, float acc[4][4][4])
{
    const uint32_t sbase = smem_to_u32(smem);
    const int tid = threadIdx.x;
    const int w = tid >> 5;
    const int l = tid & 31;
    const int warp_m = w >> 2;
    const int warp_n = w & 3;

    const int mat = l >> 3, lr = l & 7;
    const int a_row  = warp_m * 64 + (mat & 1) * 8 + lr;
    const int a_koff = (mat >> 1) * 16;
    const int b_row  = warp_n * 32 + (mat >> 1) * 8 + lr;
    const int b_koff = (mat & 1) * 16;

    const int ld_r0 = tid >> 2;
    const int ld_c  = (tid & 3) * 16;
    const int ld_k  = (tid & 3) * 8;

#define ISSUE_STAGE(s_)                                                        \
    do {                                                                       \
        const int k0_ = (s_) * KCH;                                            \
        const uint32_t st_ = sbase + ((s_) % 3) * STAGE_B;                     \
        const __nv_bfloat16* gsrc_[4] = {Ah, Al, Bh, Bl};                      \
        const int grow_[4] = {m0, m0, n0, n0};                                 \
        _Pragma("unroll")                                                      \
        for (int tI = 0; tI < 4; tI++) {                                       \
            _Pragma("unroll")                                                  \
            for (int i = 0; i < 2; i++) {                                      \
                int r_ = ld_r0 + i * 64;                                       \
                uint32_t dst_ = st_ + tI * TILE_B + r_ * ROW_STR + ld_c;       \
                const __nv_bfloat16* src_ =                                    \
                    gsrc_[tI] + (size_t)(grow_[tI] + r_) * D_ + k0_ + ld_k;    \
                CP_ASYNC16(dst_, src_);                                        \
            }                                                                  \
        }                                                                      \
        CP_COMMIT();                                                           \
    } while (0)

    ISSUE_STAGE(0);
    ISSUE_STAGE(1);

    for (int s = 0; s < 32; s++) {
        if (s < 31) CP_WAIT(1);
        else        CP_WAIT(0);
        __syncthreads();
        if (s + 2 < 32) ISSUE_STAGE(s + 2);

        const uint32_t st = sbase + (s % 3) * STAGE_B;
#pragma unroll
        for (int ks = 0; ks < 2; ks++) {
            const uint32_t kb = ks * 32;
            uint32_t ah[4][4], al[4][4], bh[2][4], bl[2][4];
#pragma unroll
            for (int mt = 0; mt < 4; mt++) {
                uint32_t addr = st + (a_row + mt * 16) * ROW_STR + kb + a_koff;
                LDMATRIX_X4(ah[mt][0], ah[mt][1], ah[mt][2], ah[mt][3], addr);
                LDMATRIX_X4(al[mt][0], al[mt][1], al[mt][2], al[mt][3],
                            addr + TILE_B);
            }
#pragma unroll
            for (int pr = 0; pr < 2; pr++) {
                uint32_t addr = st + 2 * TILE_B +
                                (b_row + pr * 16) * ROW_STR + kb + b_koff;
                LDMATRIX_X4(bh[pr][0], bh[pr][1], bh[pr][2], bh[pr][3], addr);
                LDMATRIX_X4(bl[pr][0], bl[pr][1], bl[pr][2], bl[pr][3],
                            addr + TILE_B);
            }
#pragma unroll
            for (int mt = 0; mt < 4; mt++) {
#pragma unroll
                for (int nt = 0; nt < 4; nt++) {
                    const int p = nt >> 1, q = (nt & 1) * 2;
                    MMA_BF16(acc[mt][nt], ah[mt], bh[p][q], bh[p][q + 1]);
                    MMA_BF16(acc[mt][nt], ah[mt], bl[p][q], bl[p][q + 1]);
                    MMA_BF16(acc[mt][nt], al[mt], bh[p][q], bh[p][q + 1]);
                }
            }
        }
    }
#undef ISSUE_STAGE
}

#define SCL 0.18033688011112042f         // 0.125 * log2(e), folded into Q

// ---------------------------------------------------------------------------
// Fused QKV projection: z=0 Q(+rope, +SCL), z=1 K(+rope), z=2 V.
// ---------------------------------------------------------------------------
__global__ __launch_bounds__(256) void hmma_qkv_kernel(const int* __restrict__ tp32)
{
    extern __shared__ char smem[];
    const int z = blockIdx.z;
    const __nv_bfloat16* Bh = (z == 0) ? g_wqh : (z == 1) ? g_wkh : g_wvh;
    const __nv_bfloat16* Bl = (z == 0) ? g_wql : (z == 1) ? g_wkl : g_wvl;
    __nv_bfloat16* Oh = (z == 0) ? g_qbh : (z == 1) ? g_kbh : g_vbh;
    __nv_bfloat16* Ol = (z == 0) ? g_qbl : (z == 1) ? g_kbl : g_vbl;
    const int rope = (z < 2);
    const float oscale = (z == 0) ? SCL : 1.0f;

    const int n0 = blockIdx.x * 128;
    const int m0 = blockIdx.y * 128;

    float acc[4][4][4];
#pragma unroll
    for (int mt = 0; mt < 4; mt++)
#pragma unroll
        for (int nt = 0; nt < 4; nt++)
#pragma unroll
            for (int r = 0; r < 4; r++) acc[mt][nt][r] = 0.f;

    gemm_core(g_xh, g_xl, Bh, Bl, m0, n0, smem, acc);

    const int w = threadIdx.x >> 5, l = threadIdx.x & 31;
    const int warp_m = w >> 2, warp_n = w & 3;
    const int qr = l >> 2, qc = (l & 3) * 2;

#pragma unroll
    for (int mt = 0; mt < 4; mt++) {
        const int r0 = m0 + warp_m * 64 + mt * 16 + qr;
        const int r1 = r0 + 8;
        const float *cb0 = 0, *sb0 = 0, *cb1 = 0, *sb1 = 0;
        if (rope) {
            int p0 = get_pos(tp32, r0 & (S_ - 1));
            int p1 = get_pos(tp32, r1 & (S_ - 1));
            cb0 = g_cos + p0 * (DK / 2); sb0 = g_sin + p0 * (DK / 2);
            cb1 = g_cos + p1 * (DK / 2); sb1 = g_sin + p1 * (DK / 2);
        }
        const int b0i = r0 >> 11, s0i = r0 & (S_ - 1);
        const int b1i = r1 >> 11, s1i = r1 & (S_ - 1);
#pragma unroll
        for (int nt = 0; nt < 4; nt++) {
            const int col = n0 + warp_n * 32 + nt * 8 + qc;
            const int h = col >> 6, d = col & 63;
            float c0 = acc[mt][nt][0], c1 = acc[mt][nt][1];
            float c2 = acc[mt][nt][2], c3 = acc[mt][nt][3];
            if (rope) {
                const int pj = d >> 1;
                float cc = cb0[pj], ss = sb0[pj];
                float e = c0, o = c1;
                c0 = e * cc - o * ss; c1 = o * cc + e * ss;
                cc = cb1[pj]; ss = sb1[pj];
                e = c2; o = c3;
                c2 = e * cc - o * ss; c3 = o * cc + e * ss;
            }
            c0 *= oscale; c1 *= oscale; c2 *= oscale; c3 *= oscale;
            uint32_t rh, rl;
            size_t i0 = (((size_t)(b0i * H_ + h) * S_ + s0i) * DK + d) >> 1;
            size_t i1 = (((size_t)(b1i * H_ + h) * S_ + s1i) * DK + d) >> 1;
            split_pack(c0, c1, rh, rl);
            ((uint32_t*)Oh)[i0] = rh; ((uint32_t*)Ol)[i0] = rl;
            split_pack(c2, c3, rh, rl);
            ((uint32_t*)Oh)[i1] = rh; ((uint32_t*)Ol)[i1] = rl;
        }
    }
}

// ---------------------------------------------------------------------------
// Output projection: fp32 out = att @ Wo
// ---------------------------------------------------------------------------
__global__ __launch_bounds__(256) void hmma_o_kernel(float* __restrict__ C)
{
    extern __shared__ char smem[];
    const int n0 = blockIdx.x * 128;
    const int m0 = blockIdx.y * 128;

    float acc[4][4][4];
#pragma unroll
    for (int mt = 0; mt < 4; mt++)
#pragma unroll
        for (int nt = 0; nt < 4; nt++)
#pragma unroll
            for (int r = 0; r < 4; r++) acc[mt][nt][r] = 0.f;

    gemm_core(g_ath, g_atl, g_woh, g_wol, m0, n0, smem, acc);

    const int w = threadIdx.x >> 5, l = threadIdx.x & 31;
    const int warp_m = w >> 2, warp_n = w & 3;
    const int qr = l >> 2, qc = (l & 3) * 2;
#pragma unroll
    for (int mt = 0; mt < 4; mt++) {
        const int r0 = m0 + warp_m * 64 + mt * 16 + qr;
        const int r1 = r0 + 8;
#pragma unroll
        for (int nt = 0; nt < 4; nt++) {
            const int col = n0 + warp_n * 32 + nt * 8 + qc;
            *(float2*)(C + (size_t)r0 * D_ + col) =
                make_float2(acc[mt][nt][0], acc[mt][nt][1]);
            *(float2*)(C + (size_t)r1 * D_ + col) =
                make_float2(acc[mt][nt][2], acc[mt][nt][3]);
        }
    }
}

// ---------------------------------------------------------------------------
// Flash attention, split-bf16 HMMA, causal. 3-stage KV pipeline, one sync/iter.
// ---------------------------------------------------------------------------
#define KV_STRIDE 144
#define KV_TILE   (64 * KV_STRIDE)       // 9216
#define FL_STAGE  (4 * KV_TILE)          // 36864: Kh, Kl, Vh, Vl
#define FL_SMEM   (3 * FL_STAGE)         // 110592

__global__ __launch_bounds__(256) void flash_hmma_kernel()
{
    extern __shared__ char fs[];
    const uint32_t sbase = smem_to_u32(fs);
    const int tid = threadIdx.x;
    const int w = tid >> 5, l = tid & 31;
    const int qt = 15 - blockIdx.x;          // long blocks first
    const int bh = blockIdx.y;
    const int mat = l >> 3, lr = l & 7;
    const int qr = l >> 2, qc = (l & 3) * 2;

    const size_t bh_off = (size_t)bh * S_ * DK;
    const __nv_bfloat16* qh_g = g_qbh + bh_off + (size_t)qt * 128 * DK;
    const __nv_bfloat16* ql_g = g_qbl + bh_off + (size_t)qt * 128 * DK;
    const __nv_bfloat16* kh_g = g_kbh + bh_off;
    const __nv_bfloat16* kl_g = g_kbl + bh_off;
    const __nv_bfloat16* vh_g = g_vbh + bh_off;
    const __nv_bfloat16* vl_g = g_vbl + bh_off;

    // ---- load Q tile (128x64 hi + lo) into stage-0 area, extract frags ----
    {
#pragma unroll
        for (int t = 0; t < 2; t++) {
            const __nv_bfloat16* src = t ? ql_g : qh_g;
#pragma unroll
            for (int i = 0; i < 4; i++) {
                int p = tid + i * 256;
                int rr = p >> 3, cc = p & 7;
                CP_ASYNC16(sbase + t * 18432 + rr * KV_STRIDE + cc * 16,
                           src + (size_t)rr * DK + cc * 8);
            }
        }
        CP_COMMIT();
        CP_WAIT(0);
        __syncthreads();
    }
    uint32_t qhf[4][4], qlf[4][4];
#pragma unroll
    for (int ks = 0; ks < 4; ks++) {
        uint32_t addr = sbase + (w * 16 + (mat & 1) * 8 + lr) * KV_STRIDE +
                        ks * 32 + (mat >> 1) * 16;
        LDMATRIX_X4(qhf[ks][0], qhf[ks][1], qhf[ks][2], qhf[ks][3], addr);
        LDMATRIX_X4(qlf[ks][0], qlf[ks][1], qlf[ks][2], qlf[ks][3], addr + 18432);
    }
    __syncthreads();

    // ---- state ----
    float m0 = -1e30f, m1 = -1e30f, l0 = 0.f, l1 = 0.f;
    float ob[8][4];
#pragma unroll
    for (int j = 0; j < 8; j++)
#pragma unroll
        for (int r = 0; r < 4; r++) ob[j][r] = 0.f;

    const int r0g = qt * 128 + w * 16 + qr;
    const int r1g = r0g + 8;
    const int ktmax = 2 * qt + 1;   // >= 1 always

#define FL_ISSUE(kt_)                                                          \
    do {                                                                       \
        const uint32_t st_ = sbase + ((kt_) % 3) * FL_STAGE;                   \
        const __nv_bfloat16* gs_[4] = {kh_g, kl_g, vh_g, vl_g};                \
        _Pragma("unroll")                                                      \
        for (int t = 0; t < 4; t++) {                                          \
            _Pragma("unroll")                                                  \
            for (int i = 0; i < 2; i++) {                                      \
                int p = tid + i * 256;                                         \
                int rr = p >> 3, cc = p & 7;                                   \
                CP_ASYNC16(st_ + t * KV_TILE + rr * KV_STRIDE + cc * 16,       \
                           gs_[t] + (size_t)((kt_) * 64 + rr) * DK + cc * 8);  \
            }                                                                  \
        }                                                                      \
        CP_COMMIT();                                                           \
    } while (0)

    FL_ISSUE(0);
    FL_ISSUE(1);

    for (int kt = 0; kt <= ktmax; kt++) {
        if (kt < ktmax) CP_WAIT(1);
        else            CP_WAIT(0);
        __syncthreads();
        if (kt + 2 <= ktmax) FL_ISSUE(kt + 2);

        const uint32_t st = sbase + (kt % 3) * FL_STAGE;

        // ---- scores: S = Qh*Kh + Qh*Kl + Ql*Kh (Q pre-scaled by SCL) ----
        float sc[8][4];
#pragma unroll
        for (int j = 0; j < 8; j++)
#pragma unroll
            for (int r = 0; r < 4; r++) sc[j][r] = 0.f;

#pragma unroll
        for (int ks = 0; ks < 4; ks++) {
            uint32_t kh4[4][4], kl4[4][4];
#pragma unroll
            for (int t = 0; t < 4; t++) {
                uint32_t addr = st + (t * 16 + (mat >> 1) * 8 + lr) * KV_STRIDE +
                                ks * 32 + (mat & 1) * 16;
                LDMATRIX_X4(kh4[t][0], kh4[t][1], kh4[t][2], kh4[t][3], addr);
                LDMATRIX_X4(kl4[t][0], kl4[t][1], kl4[t][2], kl4[t][3],
                            addr + KV_TILE);
            }
#pragma unroll
            for (int j = 0; j < 8; j++) {
                const int t = j >> 1, q = (j & 1) * 2;
                MMA_BF16(sc[j], qhf[ks], kh4[t][q], kh4[t][q + 1]);
                MMA_BF16(sc[j], qhf[ks], kl4[t][q], kl4[t][q + 1]);
                MMA_BF16(sc[j], qlf[ks], kh4[t][q], kh4[t][q + 1]);
            }
        }

        // ---- causal mask (scores already in log2 domain) ----
        if (kt >= 2 * qt) {
            const int cb = kt * 64;
#pragma unroll
            for (int j = 0; j < 8; j++) {
                int c0 = cb + j * 8 + qc, c1 = c0 + 1;
                if (c0 > r0g) sc[j][0] = -30000.f;
                if (c1 > r0g) sc[j][1] = -30000.f;
                if (c0 > r1g) sc[j][2] = -30000.f;
                if (c1 > r1g) sc[j][3] = -30000.f;
            }
        }

        // ---- online softmax (exp2 domain) ----
        float tm0 = -1e30f, tm1 = -1e30f;
#pragma unroll
        for (int j = 0; j < 8; j++) {
            tm0 = fmaxf(tm0, fmaxf(sc[j][0], sc[j][1]));
            tm1 = fmaxf(tm1, fmaxf(sc[j][2], sc[j][3]));
        }
        tm0 = fmaxf(tm0, __shfl_xor_sync(0xffffffffu, tm0, 1));
        tm0 = fmaxf(tm0, __shfl_xor_sync(0xffffffffu, tm0, 2));
        tm1 = fmaxf(tm1, __shfl_xor_sync(0xffffffffu, tm1, 1));
        tm1 = fmaxf(tm1, __shfl_xor_sync(0xffffffffu, tm1, 2));
        const float nm0 = fmaxf(m0, tm0), nm1 = fmaxf(m1, tm1);
        const float cor0 = exp2f_fast(m0 - nm0);
        const float cor1 = exp2f_fast(m1 - nm1);
        float s0 = 0.f, s1 = 0.f;
#pragma unroll
        for (int j = 0; j < 8; j++) {
            sc[j][0] = exp2f_fast(sc[j][0] - nm0);
            sc[j][1] = exp2f_fast(sc[j][1] - nm0);
            sc[j][2] = exp2f_fast(sc[j][2] - nm1);
            sc[j][3] = exp2f_fast(sc[j][3] - nm1);
            s0 += sc[j][0] + sc[j][1];
            s1 += sc[j][2] + sc[j][3];
        }
        s0 += __shfl_xor_sync(0xffffffffu, s0, 1);
        s0 += __shfl_xor_sync(0xffffffffu, s0, 2);
        s1 += __shfl_xor_sync(0xffffffffu, s1, 1);
        s1 += __shfl_xor_sync(0xffffffffu, s1, 2);
        l0 = l0 * cor0 + s0;
        l1 = l1 * cor1 + s1;
        m0 = nm0; m1 = nm1;
#pragma unroll
        for (int j = 0; j < 8; j++) {
            ob[j][0] *= cor0; ob[j][1] *= cor0;
            ob[j][2] *= cor1; ob[j][3] *= cor1;
        }

        // ---- PV: O += Ph*Vh + Ph*Vl + Pl*Vh ----
#pragma unroll
        for (int ks = 0; ks < 4; ks++) {
            uint32_t pah[4], pal[4];
            split_pack(sc[2 * ks][0], sc[2 * ks][1], pah[0], pal[0]);
            split_pack(sc[2 * ks][2], sc[2 * ks][3], pah[1], pal[1]);
            split_pack(sc[2 * ks + 1][0], sc[2 * ks + 1][1], pah[2], pal[2]);
            split_pack(sc[2 * ks + 1][2], sc[2 * ks + 1][3], pah[3], pal[3]);

            uint32_t vh4[4][4], vl4[4][4];
#pragma unroll
            for (int t = 0; t < 4; t++) {
                uint32_t addr = st + 2 * KV_TILE +
                                (ks * 16 + (mat & 1) * 8 + lr) * KV_STRIDE +
                                t * 32 + (mat >> 1) * 16;
                LDMATRIX_X4_T(vh4[t][0], vh4[t][1], vh4[t][2], vh4[t][3], addr);
                LDMATRIX_X4_T(vl4[t][0], vl4[t][1], vl4[t][2], vl4[t][3],
                              addr + KV_TILE);
            }
#pragma unroll
            for (int j = 0; j < 8; j++) {
                const int t = j >> 1, q = (j & 1) * 2;
                MMA_BF16(ob[j], pah, vh4[t][q], vh4[t][q + 1]);
                MMA_BF16(ob[j], pah, vl4[t][q], vl4[t][q + 1]);
                MMA_BF16(ob[j], pal, vh4[t][q], vh4[t][q + 1]);
            }
        }
    }
#undef FL_ISSUE

    // ---- epilogue: normalize, split bf16, write row-major att layout ----
    const float inv0 = 1.f / l0, inv1 = 1.f / l1;
    const int b = bh >> 4, h = bh & 15;
    const size_t row0 = (size_t)b * S_ + r0g;
    const size_t row1 = row0 + 8;
    uint32_t* oh32 = (uint32_t*)g_ath;
    uint32_t* ol32 = (uint32_t*)g_atl;
#pragma unroll
    for (int j = 0; j < 8; j++) {
        const int col = h * 64 + j * 8 + qc;
        uint32_t rh, rl;
        split_pack(ob[j][0] * inv0, ob[j][1] * inv0, rh, rl);
        oh32[(row0 * D_ + col) >> 1] = rh;
        ol32[(row0 * D_ + col) >> 1] = rl;
        split_pack(ob[j][2] * inv1, ob[j][3] * inv1, rh, rl);
        oh32[(row1 * D_ + col) >> 1] = rh;
        ol32[(row1 * D_ + col) >> 1] = rl;
    }
}

// ---------------------------------------------------------------------------
// Launcher. 8 launches/replay; ncu (-s 5 -c 1) captures launch #6 = hmma_qkv.
// ---------------------------------------------------------------------------
extern "C" void kernel_launch(void* const* d_in, const int* in_sizes, int n_in,
                              void* d_out, int out_size)
{
    const float* x    = (const float*)d_in[0];
    const float* wq   = (const float*)d_in[1];
    const float* wk   = (const float*)d_in[2];
    const float* wv   = (const float*)d_in[3];
    const float* wo   = (const float*)d_in[4];
    const int*   tp32 = (const int*)d_in[5];
    (void)in_sizes; (void)n_in; (void)out_size;

    cudaFuncSetAttribute(hmma_qkv_kernel,
                         cudaFuncAttributeMaxDynamicSharedMemorySize, GEMM_SMEM);
    cudaFuncSetAttribute(hmma_o_kernel,
                         cudaFuncAttributeMaxDynamicSharedMemorySize, GEMM_SMEM);
    cudaFuncSetAttribute(flash_hmma_kernel,
                         cudaFuncAttributeMaxDynamicSharedMemorySize, FL_SMEM);

    void *pxh, *pxl;
    void *pwqh, *pwql, *pwkh, *pwkl, *pwvh, *pwvl, *pwoh, *pwol;
    cudaGetSymbolAddress(&pxh, g_xh);
    cudaGetSymbolAddress(&pxl, g_xl);
    cudaGetSymbolAddress(&pwqh, g_wqh);
    cudaGetSymbolAddress(&pwql, g_wql);
    cudaGetSymbolAddress(&pwkh, g_wkh);
    cudaGetSymbolAddress(&pwkl, g_wkl);
    cudaGetSymbolAddress(&pwvh, g_wvh);
    cudaGetSymbolAddress(&pwvl, g_wvl);
    cudaGetSymbolAddress(&pwoh, g_woh);
    cudaGetSymbolAddress(&pwol, g_wol);

    const int NX = M_ * D_;
    dim3 tb(32, 8), tg(32, 32);

    // 1. split x (+ RoPE tables)
    split_kernel<<<(NX + 255) / 256, 256>>>(x, (__nv_bfloat16*)pxh,
                                            (__nv_bfloat16*)pxl, NX);
    // 2-5. weight transpose+split
    wsplit_kernel<<<tg, tb>>>(wq, (__nv_bfloat16*)pwqh, (__nv_bfloat16*)pwql);
    wsplit_kernel<<<tg, tb>>>(wk, (__nv_bfloat16*)pwkh, (__nv_bfloat16*)pwkl);
    wsplit_kernel<<<tg, tb>>>(wv, (__nv_bfloat16*)pwvh, (__nv_bfloat16*)pwvl);
    wsplit_kernel<<<tg, tb>>>(wo, (__nv_bfloat16*)pwoh, (__nv_bfloat16*)pwol);

    // 6. fused QKV projections — ncu capture lands here
    dim3 gqkv(D_ / 128, M_ / 128, 3);
    hmma_qkv_kernel<<<gqkv, 256, GEMM_SMEM>>>(tp32);

    // 7. flash attention
    dim3 gf(16, B_ * H_);
    flash_hmma_kernel<<<gf, 256, FL_SMEM>>>();

    // 8. output projection (fp32 to d_out)
    dim3 gg(D_ / 128, M_ / 128);
    hmma_o_kernel<<<gg, 256, GEMM_SMEM>>>((float*)d_out);
}

// round 14
// speedup vs baseline: 1.1833x; 1.1833x over previous
#include <cuda_runtime.h>
#include <cuda_bf16.h>
#include <cuda_fp16.h>
#include <math.h>
#include <stdint.h>

// Problem constants
#define B_   4
#define S_   2048
#define D_   1024
#define H_   16
#define DK   64
#define MSEQ 2048
#define M_   (B_ * S_)   // 8192

// ---------------------------------------------------------------------------
// Scratch (__device__ globals; no allocations allowed)
// ---------------------------------------------------------------------------
__device__ float g_cos[MSEQ * (DK / 2)];
__device__ float g_sin[MSEQ * (DK / 2)];

__device__ __align__(16) __nv_bfloat16 g_xh[M_ * D_];
__device__ __align__(16) __nv_bfloat16 g_xl[M_ * D_];
__device__ __align__(16) __nv_bfloat16 g_ath[M_ * D_];
__device__ __align__(16) __nv_bfloat16 g_atl[M_ * D_];
__device__ __align__(16) __nv_bfloat16 g_qbh[M_ * D_];
__device__ __align__(16) __nv_bfloat16 g_qbl[M_ * D_];
__device__ __align__(16) __nv_bfloat16 g_kbh[M_ * D_];
__device__ __align__(16) __nv_bfloat16 g_kbl[M_ * D_];
__device__ __align__(16) __half        g_vf [M_ * D_];   // V: single fp16
__device__ __align__(16) __nv_bfloat16 g_wqh[D_ * D_];
__device__ __align__(16) __nv_bfloat16 g_wql[D_ * D_];
__device__ __align__(16) __nv_bfloat16 g_wkh[D_ * D_];
__device__ __align__(16) __nv_bfloat16 g_wkl[D_ * D_];
__device__ __align__(16) __nv_bfloat16 g_wvh[D_ * D_];
__device__ __align__(16) __nv_bfloat16 g_wvl[D_ * D_];
__device__ __align__(16) __nv_bfloat16 g_woh[D_ * D_];
__device__ __align__(16) __nv_bfloat16 g_wol[D_ * D_];

// ---------------------------------------------------------------------------
// PTX helpers (sm_80+ only; harness compiles for plain sm_103 — no tcgen05)
// ---------------------------------------------------------------------------
__device__ __forceinline__ uint32_t smem_to_u32(const void* p) {
    uint32_t a;
    asm("{ .reg .u64 t; cvta.to.shared.u64 t, %1; cvt.u32.u64 %0, t; }"
        : "=r"(a) : "l"(p));
    return a;
}
#define CP_ASYNC16(dst_u32, src_ptr) \
    asm volatile("cp.async.cg.shared.global [%0], [%1], 16;" \
                 :: "r"(dst_u32), "l"(src_ptr))
#define CP_COMMIT() asm volatile("cp.async.commit_group;" ::: "memory")
#define CP_WAIT(n) asm volatile("cp.async.wait_group %0;" :: "n"(n) : "memory")
#define LDMATRIX_X4(r0, r1, r2, r3, addr) \
    asm volatile("ldmatrix.sync.aligned.m8n8.x4.shared.b16 {%0,%1,%2,%3}, [%4];" \
                 : "=r"(r0), "=r"(r1), "=r"(r2), "=r"(r3) : "r"(addr))
#define LDMATRIX_X4_T(r0, r1, r2, r3, addr) \
    asm volatile("ldmatrix.sync.aligned.m8n8.x4.trans.shared.b16 {%0,%1,%2,%3}, [%4];" \
                 : "=r"(r0), "=r"(r1), "=r"(r2), "=r"(r3) : "r"(addr))
#define MMA_BF16(c, a, b0, b1) \
    asm volatile("mma.sync.aligned.m16n8k16.row.col.f32.bf16.bf16.f32 " \
                 "{%0,%1,%2,%3}, {%4,%5,%6,%7}, {%8,%9}, {%0,%1,%2,%3};" \
                 : "+f"((c)[0]), "+f"((c)[1]), "+f"((c)[2]), "+f"((c)[3]) \
                 : "r"((a)[0]), "r"((a)[1]), "r"((a)[2]), "r"((a)[3]), \
                   "r"(b0), "r"(b1))
#define MMA_F16(c, a, b0, b1) \
    asm volatile("mma.sync.aligned.m16n8k16.row.col.f32.f16.f16.f32 " \
                 "{%0,%1,%2,%3}, {%4,%5,%6,%7}, {%8,%9}, {%0,%1,%2,%3};" \
                 : "+f"((c)[0]), "+f"((c)[1]), "+f"((c)[2]), "+f"((c)[3]) \
                 : "r"((a)[0]), "r"((a)[1]), "r"((a)[2]), "r"((a)[3]), \
                   "r"(b0), "r"(b1))

__device__ __forceinline__ uint32_t pack_bf16x2(float lo, float hi) {
    uint32_t r;
    asm("cvt.rn.bf16x2.f32 %0, %1, %2;" : "=r"(r) : "f"(hi), "f"(lo));
    return r;
}
__device__ __forceinline__ void split_pack(float v0, float v1,
                                           uint32_t& rh, uint32_t& rl) {
    rh = pack_bf16x2(v0, v1);
    float h0 = __uint_as_float(rh << 16);
    float h1 = __uint_as_float(rh & 0xffff0000u);
    rl = pack_bf16x2(v0 - h0, v1 - h1);
}
__device__ __forceinline__ uint32_t pack_f16x2(float v0, float v1) {
    __half2 h = __floats2half2_rn(v0, v1);   // low = v0, high = v1
    return *(uint32_t*)&h;
}

// fast exp2, FFMA-only (no MUFU). |err| ~ 2e-6 relative.
__device__ __forceinline__ float exp2f_fast(float x) {
    x = fmaxf(x, -120.f);
    float z = __fadd_rn(x, 12582912.f);
    int ei = __float_as_int(z) - 0x4B400000;
    float f = x - __fadd_rn(z, -12582912.f);
    float p = 0.0013333558f;
    p = fmaf(p, f, 0.0096181291f);
    p = fmaf(p, f, 0.0555041087f);
    p = fmaf(p, f, 0.2402265070f);
    p = fmaf(p, f, 0.69314718056f);
    p = fmaf(p, f, 1.0f);
    return __int_as_float(__float_as_int(p) + (ei << 23));
}

__device__ __forceinline__ int get_pos(const int* __restrict__ tp32, int s) {
    return (tp32[1] == 0) ? tp32[2 * s] : tp32[s];
}

// ---------------------------------------------------------------------------
// split x (fp32 -> bf16 hi/lo) + RoPE tables folded in
// ---------------------------------------------------------------------------
__global__ void split_kernel(const float* __restrict__ in,
                             __nv_bfloat16* __restrict__ hi,
                             __nv_bfloat16* __restrict__ lo, int n)
{
    int i = blockIdx.x * blockDim.x + threadIdx.x;
    if (i < MSEQ * (DK / 2)) {
        int pos = i >> 5;
        int j   = i & 31;
        double freq = pow(10000.0, -(double)(2 * j) / (double)DK);
        double ang  = (double)pos * freq;
        g_cos[i] = (float)cos(ang);
        g_sin[i] = (float)sin(ang);
    }
    if (i < n) {
        float v = in[i];
        __nv_bfloat16 h = __float2bfloat16(v);
        hi[i] = h;
        lo[i] = __float2bfloat16(v - __bfloat162float(h));
    }
}

// ---------------------------------------------------------------------------
// Fused weight transpose + split for all 4 weights: z picks the matrix.
// ---------------------------------------------------------------------------
__global__ void wsplit4_kernel(const float* __restrict__ wq,
                               const float* __restrict__ wk,
                               const float* __restrict__ wv,
                               const float* __restrict__ wo)
{
    __shared__ float t[32][33];
    const int z = blockIdx.z;
    const float* W = (z == 0) ? wq : (z == 1) ? wk : (z == 2) ? wv : wo;
    __nv_bfloat16* th = (z == 0) ? g_wqh : (z == 1) ? g_wkh : (z == 2) ? g_wvh : g_woh;
    __nv_bfloat16* tl = (z == 0) ? g_wql : (z == 1) ? g_wkl : (z == 2) ? g_wvl : g_wol;

    int bx = blockIdx.x * 32;
    int by = blockIdx.y * 32;
    int tx = threadIdx.x, ty = threadIdx.y;
    for (int i = ty; i < 32; i += 8)
        t[i][tx] = W[(size_t)(by + i) * D_ + bx + tx];
    __syncthreads();
    for (int i = ty; i < 32; i += 8) {
        float v = t[tx][i];
        __nv_bfloat16 h = __float2bfloat16(v);
        size_t o = (size_t)(bx + i) * D_ + by + tx;
        th[o] = h;
        tl[o] = __float2bfloat16(v - __bfloat162float(h));
    }
}

// ---------------------------------------------------------------------------
// HMMA GEMM core (R8-proven): 2-stage double buffer.
// ---------------------------------------------------------------------------
#define KCH      32
#define ROW_STR  80
#define TILE_B   (128 * ROW_STR)
#define STAGE_B  (4 * TILE_B)            // 40960: Ah, Al, Bh, Bl
#define GEMM_SMEM (2 * STAGE_B)          // 81920 -> 2 CTAs/SM

__device__ __forceinline__ void gemm_core(
    const __nv_bfloat16* __restrict__ Ah, const __nv_bfloat16* __restrict__ Al,
    const __nv_bfloat16* __restrict__ Bh, const __nv_bfloat16* __restrict__ Bl,
    int m0, int n0, char* smem, float acc[4][4][4])
{
    const uint32_t sbase = smem_to_u32(smem);
    const int tid = threadIdx.x;
    const int w = tid >> 5;
    const int l = tid & 31;
    const int warp_m = w >> 2;
    const int warp_n = w & 3;

    const int mat = l >> 3, lr = l & 7;
    const int a_row  = warp_m * 64 + (mat & 1) * 8 + lr;
    const int a_koff = (mat >> 1) * 16;
    const int b_row  = warp_n * 32 + (mat >> 1) * 8 + lr;
    const int b_koff = (mat & 1) * 16;

    const int ld_r0 = tid >> 2;
    const int ld_c  = (tid & 3) * 16;
    const int ld_k  = (tid & 3) * 8;

#define ISSUE_STAGE(s_)                                                        \
    do {                                                                       \
        const int k0_ = (s_) * KCH;                                            \
        const uint32_t st_ = sbase + ((s_) & 1) * STAGE_B;                     \
        const __nv_bfloat16* gsrc_[4] = {Ah, Al, Bh, Bl};                      \
        const int grow_[4] = {m0, m0, n0, n0};                                 \
        _Pragma("unroll")                                                      \
        for (int tI = 0; tI < 4; tI++) {                                       \
            _Pragma("unroll")                                                  \
            for (int i = 0; i < 2; i++) {                                      \
                int r_ = ld_r0 + i * 64;                                       \
                uint32_t dst_ = st_ + tI * TILE_B + r_ * ROW_STR + ld_c;       \
                const __nv_bfloat16* src_ =                                    \
                    gsrc_[tI] + (size_t)(grow_[tI] + r_) * D_ + k0_ + ld_k;    \
                CP_ASYNC16(dst_, src_);                                        \
            }                                                                  \
        }                                                                      \
        CP_COMMIT();                                                           \
    } while (0)

    ISSUE_STAGE(0);

    for (int s = 0; s < 32; s++) {
        if (s + 1 < 32) {
            ISSUE_STAGE(s + 1);
            CP_WAIT(1);
        } else {
            CP_WAIT(0);
        }
        __syncthreads();

        const uint32_t st = sbase + (s & 1) * STAGE_B;
#pragma unroll
        for (int ks = 0; ks < 2; ks++) {
            const uint32_t kb = ks * 32;
            uint32_t ah[4][4], al[4][4], bh[2][4], bl[2][4];
#pragma unroll
            for (int mt = 0; mt < 4; mt++) {
                uint32_t addr = st + (a_row + mt * 16) * ROW_STR + kb + a_koff;
                LDMATRIX_X4(ah[mt][0], ah[mt][1], ah[mt][2], ah[mt][3], addr);
                LDMATRIX_X4(al[mt][0], al[mt][1], al[mt][2], al[mt][3],
                            addr + TILE_B);
            }
#pragma unroll
            for (int pr = 0; pr < 2; pr++) {
                uint32_t addr = st + 2 * TILE_B +
                                (b_row + pr * 16) * ROW_STR + kb + b_koff;
                LDMATRIX_X4(bh[pr][0], bh[pr][1], bh[pr][2], bh[pr][3], addr);
                LDMATRIX_X4(bl[pr][0], bl[pr][1], bl[pr][2], bl[pr][3],
                            addr + TILE_B);
            }
#pragma unroll
            for (int mt = 0; mt < 4; mt++) {
#pragma unroll
                for (int nt = 0; nt < 4; nt++) {
                    const int p = nt >> 1, q = (nt & 1) * 2;
                    MMA_BF16(acc[mt][nt], ah[mt], bh[p][q], bh[p][q + 1]);
                    MMA_BF16(acc[mt][nt], ah[mt], bl[p][q], bl[p][q + 1]);
                    MMA_BF16(acc[mt][nt], al[mt], bh[p][q], bh[p][q + 1]);
                }
            }
        }
        __syncthreads();
    }
#undef ISSUE_STAGE
}

#define SCL 0.18033688011112042f         // 0.125 * log2(e), folded into Q

// ---------------------------------------------------------------------------
// Fused QKV projection: z=0 Q(+rope, +SCL), z=1 K(+rope), z=2 V (fp16 single).
// ---------------------------------------------------------------------------
__global__ __launch_bounds__(256) void hmma_qkv_kernel(const int* __restrict__ tp32)
{
    extern __shared__ char smem[];
    const int z = blockIdx.z;
    const __nv_bfloat16* Bh = (z == 0) ? g_wqh : (z == 1) ? g_wkh : g_wvh;
    const __nv_bfloat16* Bl = (z == 0) ? g_wql : (z == 1) ? g_wkl : g_wvl;
    const int rope = (z < 2);
    const float oscale = (z == 0) ? SCL : 1.0f;

    const int n0 = blockIdx.x * 128;
    const int m0 = blockIdx.y * 128;

    float acc[4][4][4];
#pragma unroll
    for (int mt = 0; mt < 4; mt++)
#pragma unroll
        for (int nt = 0; nt < 4; nt++)
#pragma unroll
            for (int r = 0; r < 4; r++) acc[mt][nt][r] = 0.f;

    gemm_core(g_xh, g_xl, Bh, Bl, m0, n0, smem, acc);

    const int w = threadIdx.x >> 5, l = threadIdx.x & 31;
    const int warp_m = w >> 2, warp_n = w & 3;
    const int qr = l >> 2, qc = (l & 3) * 2;

    uint32_t* Oh32 = (uint32_t*)((z == 0) ? g_qbh : g_kbh);
    uint32_t* Ol32 = (uint32_t*)((z == 0) ? g_qbl : g_kbl);
    uint32_t* Vf32 = (uint32_t*)g_vf;

#pragma unroll
    for (int mt = 0; mt < 4; mt++) {
        const int r0 = m0 + warp_m * 64 + mt * 16 + qr;
        const int r1 = r0 + 8;
        const float *cb0 = 0, *sb0 = 0, *cb1 = 0, *sb1 = 0;
        if (rope) {
            int p0 = get_pos(tp32, r0 & (S_ - 1));
            int p1 = get_pos(tp32, r1 & (S_ - 1));
            cb0 = g_cos + p0 * (DK / 2); sb0 = g_sin + p0 * (DK / 2);
            cb1 = g_cos + p1 * (DK / 2); sb1 = g_sin + p1 * (DK / 2);
        }
        const int b0i = r0 >> 11, s0i = r0 & (S_ - 1);
        const int b1i = r1 >> 11, s1i = r1 & (S_ - 1);
#pragma unroll
        for (int nt = 0; nt < 4; nt++) {
            const int col = n0 + warp_n * 32 + nt * 8 + qc;
            const int h = col >> 6, d = col & 63;
            float c0 = acc[mt][nt][0], c1 = acc[mt][nt][1];
            float c2 = acc[mt][nt][2], c3 = acc[mt][nt][3];
            if (rope) {
                const int pj = d >> 1;
                float cc = cb0[pj], ss = sb0[pj];
                float e = c0, o = c1;
                c0 = e * cc - o * ss; c1 = o * cc + e * ss;
                cc = cb1[pj]; ss = sb1[pj];
                e = c2; o = c3;
                c2 = e * cc - o * ss; c3 = o * cc + e * ss;
            }
            c0 *= oscale; c1 *= oscale; c2 *= oscale; c3 *= oscale;
            size_t i0 = (((size_t)(b0i * H_ + h) * S_ + s0i) * DK + d) >> 1;
            size_t i1 = (((size_t)(b1i * H_ + h) * S_ + s1i) * DK + d) >> 1;
            if (z == 2) {
                Vf32[i0] = pack_f16x2(c0, c1);
                Vf32[i1] = pack_f16x2(c2, c3);
            } else {
                uint32_t rh, rl;
                split_pack(c0, c1, rh, rl);
                Oh32[i0] = rh; Ol32[i0] = rl;
                split_pack(c2, c3, rh, rl);
                Oh32[i1] = rh; Ol32[i1] = rl;
            }
        }
    }
}

// ---------------------------------------------------------------------------
// Output projection: fp32 out = att @ Wo
// ---------------------------------------------------------------------------
__global__ __launch_bounds__(256) void hmma_o_kernel(float* __restrict__ C)
{
    extern __shared__ char smem[];
    const int n0 = blockIdx.x * 128;
    const int m0 = blockIdx.y * 128;

    float acc[4][4][4];
#pragma unroll
    for (int mt = 0; mt < 4; mt++)
#pragma unroll
        for (int nt = 0; nt < 4; nt++)
#pragma unroll
            for (int r = 0; r < 4; r++) acc[mt][nt][r] = 0.f;

    gemm_core(g_ath, g_atl, g_woh, g_wol, m0, n0, smem, acc);

    const int w = threadIdx.x >> 5, l = threadIdx.x & 31;
    const int warp_m = w >> 2, warp_n = w & 3;
    const int qr = l >> 2, qc = (l & 3) * 2;
#pragma unroll
    for (int mt = 0; mt < 4; mt++) {
        const int r0 = m0 + warp_m * 64 + mt * 16 + qr;
        const int r1 = r0 + 8;
#pragma unroll
        for (int nt = 0; nt < 4; nt++) {
            const int col = n0 + warp_n * 32 + nt * 8 + qc;
            *(float2*)(C + (size_t)r0 * D_ + col) =
                make_float2(acc[mt][nt][0], acc[mt][nt][1]);
            *(float2*)(C + (size_t)r1 * D_ + col) =
                make_float2(acc[mt][nt][2], acc[mt][nt][3]);
        }
    }
}

// ---------------------------------------------------------------------------
// Flash attention, causal. Scores: split-bf16 3-MMA. PV: single fp16 MMA.
// KV stage: Kh, Kl (bf16) + V (fp16) = 3 tiles. 2-stage double buffer.
// ---------------------------------------------------------------------------
#define KV_STRIDE 144
#define KV_TILE   (64 * KV_STRIDE)       // 9216
#define FL_STAGE  (3 * KV_TILE)          // 27648: Kh, Kl, V
#define FL_SMEM   (2 * FL_STAGE)         // 55296 -> 2 CTAs/SM (reg-limited)

__global__ __launch_bounds__(256) void flash_hmma_kernel()
{
    extern __shared__ char fs[];
    const uint32_t sbase = smem_to_u32(fs);
    const int tid = threadIdx.x;
    const int w = tid >> 5, l = tid & 31;
    const int qt = 15 - blockIdx.x;          // long blocks first
    const int bh = blockIdx.y;
    const int mat = l >> 3, lr = l & 7;
    const int qr = l >> 2, qc = (l & 3) * 2;

    const size_t bh_off = (size_t)bh * S_ * DK;
    const char* qh_g = (const char*)(g_qbh + bh_off + (size_t)qt * 128 * DK);
    const char* ql_g = (const char*)(g_qbl + bh_off + (size_t)qt * 128 * DK);
    const char* kh_g = (const char*)(g_kbh + bh_off);
    const char* kl_g = (const char*)(g_kbl + bh_off);
    const char* v_g  = (const char*)(g_vf  + bh_off);

    // ---- load Q tile (128x64 hi + lo), extract frags ----
    {
#pragma unroll
        for (int t = 0; t < 2; t++) {
            const char* src = t ? ql_g : qh_g;
#pragma unroll
            for (int i = 0; i < 4; i++) {
                int p = tid + i * 256;
                int rr = p >> 3, cc = p & 7;
                CP_ASYNC16(sbase + t * 18432 + rr * KV_STRIDE + cc * 16,
                           src + ((size_t)rr * DK + cc * 8) * 2);
            }
        }
        CP_COMMIT();
        CP_WAIT(0);
        __syncthreads();
    }
    uint32_t qhf[4][4], qlf[4][4];
#pragma unroll
    for (int ks = 0; ks < 4; ks++) {
        uint32_t addr = sbase + (w * 16 + (mat & 1) * 8 + lr) * KV_STRIDE +
                        ks * 32 + (mat >> 1) * 16;
        LDMATRIX_X4(qhf[ks][0], qhf[ks][1], qhf[ks][2], qhf[ks][3], addr);
        LDMATRIX_X4(qlf[ks][0], qlf[ks][1], qlf[ks][2], qlf[ks][3], addr + 18432);
    }
    __syncthreads();

    // ---- state ----
    float m0 = -1e30f, m1 = -1e30f, l0 = 0.f, l1 = 0.f;
    float ob[8][4];
#pragma unroll
    for (int j = 0; j < 8; j++)
#pragma unroll
        for (int r = 0; r < 4; r++) ob[j][r] = 0.f;

    const int r0g = qt * 128 + w * 16 + qr;
    const int r1g = r0g + 8;
    const int ktmax = 2 * qt + 1;

#define FL_ISSUE(kt_)                                                          \
    do {                                                                       \
        const uint32_t st_ = sbase + ((kt_) & 1) * FL_STAGE;                   \
        const char* gs_[3] = {kh_g, kl_g, v_g};                                \
        _Pragma("unroll")                                                      \
        for (int t = 0; t < 3; t++) {                                          \
            _Pragma("unroll")                                                  \
            for (int i = 0; i < 2; i++) {                                      \
                int p = tid + i * 256;                                         \
                int rr = p >> 3, cc = p & 7;                                   \
                CP_ASYNC16(st_ + t * KV_TILE + rr * KV_STRIDE + cc * 16,       \
                           gs_[t] + ((size_t)((kt_) * 64 + rr) * DK + cc * 8) * 2); \
            }                                                                  \
        }                                                                      \
        CP_COMMIT();                                                           \
    } while (0)

    FL_ISSUE(0);

    for (int kt = 0; kt <= ktmax; kt++) {
        if (kt + 1 <= ktmax) { FL_ISSUE(kt + 1); CP_WAIT(1); }
        else                 { CP_WAIT(0); }
        __syncthreads();

        const uint32_t st = sbase + (kt & 1) * FL_STAGE;

        // ---- scores: S = Qh*Kh + Qh*Kl + Ql*Kh (Q pre-scaled by SCL) ----
        float sc[8][4];
#pragma unroll
        for (int j = 0; j < 8; j++)
#pragma unroll
            for (int r = 0; r < 4; r++) sc[j][r] = 0.f;

#pragma unroll
        for (int ks = 0; ks < 4; ks++) {
            uint32_t kh4[4][4], kl4[4][4];
#pragma unroll
            for (int t = 0; t < 4; t++) {
                uint32_t addr = st + (t * 16 + (mat >> 1) * 8 + lr) * KV_STRIDE +
                                ks * 32 + (mat & 1) * 16;
                LDMATRIX_X4(kh4[t][0], kh4[t][1], kh4[t][2], kh4[t][3], addr);
                LDMATRIX_X4(kl4[t][0], kl4[t][1], kl4[t][2], kl4[t][3],
                            addr + KV_TILE);
            }
#pragma unroll
            for (int j = 0; j < 8; j++) {
                const int t = j >> 1, q = (j & 1) * 2;
                MMA_BF16(sc[j], qhf[ks], kh4[t][q], kh4[t][q + 1]);
                MMA_BF16(sc[j], qhf[ks], kl4[t][q], kl4[t][q + 1]);
                MMA_BF16(sc[j], qlf[ks], kh4[t][q], kh4[t][q + 1]);
            }
        }

        // ---- causal mask (log2 domain) ----
        if (kt >= 2 * qt) {
            const int cb = kt * 64;
#pragma unroll
            for (int j = 0; j < 8; j++) {
                int c0 = cb + j * 8 + qc, c1 = c0 + 1;
                if (c0 > r0g) sc[j][0] = -30000.f;
                if (c1 > r0g) sc[j][1] = -30000.f;
                if (c0 > r1g) sc[j][2] = -30000.f;
                if (c1 > r1g) sc[j][3] = -30000.f;
            }
        }

        // ---- online softmax (exp2 domain) ----
        float tm0 = -1e30f, tm1 = -1e30f;
#pragma unroll
        for (int j = 0; j < 8; j++) {
            tm0 = fmaxf(tm0, fmaxf(sc[j][0], sc[j][1]));
            tm1 = fmaxf(tm1, fmaxf(sc[j][2], sc[j][3]));
        }
        tm0 = fmaxf(tm0, __shfl_xor_sync(0xffffffffu, tm0, 1));
        tm0 = fmaxf(tm0, __shfl_xor_sync(0xffffffffu, tm0, 2));
        tm1 = fmaxf(tm1, __shfl_xor_sync(0xffffffffu, tm1, 1));
        tm1 = fmaxf(tm1, __shfl_xor_sync(0xffffffffu, tm1, 2));
        const float nm0 = fmaxf(m0, tm0), nm1 = fmaxf(m1, tm1);
        const float cor0 = exp2f_fast(m0 - nm0);
        const float cor1 = exp2f_fast(m1 - nm1);
        float s0 = 0.f, s1 = 0.f;
#pragma unroll
        for (int j = 0; j < 8; j++) {
            sc[j][0] = exp2f_fast(sc[j][0] - nm0);
            sc[j][1] = exp2f_fast(sc[j][1] - nm0);
            sc[j][2] = exp2f_fast(sc[j][2] - nm1);
            sc[j][3] = exp2f_fast(sc[j][3] - nm1);
            s0 += sc[j][0] + sc[j][1];
            s1 += sc[j][2] + sc[j][3];
        }
        s0 += __shfl_xor_sync(0xffffffffu, s0, 1);
        s0 += __shfl_xor_sync(0xffffffffu, s0, 2);
        s1 += __shfl_xor_sync(0xffffffffu, s1, 1);
        s1 += __shfl_xor_sync(0xffffffffu, s1, 2);
        l0 = l0 * cor0 + s0;
        l1 = l1 * cor1 + s1;
        m0 = nm0; m1 = nm1;
#pragma unroll
        for (int j = 0; j < 8; j++) {
            ob[j][0] *= cor0; ob[j][1] *= cor0;
            ob[j][2] *= cor1; ob[j][3] *= cor1;
        }

        // ---- PV: O += P (fp16) * V (fp16), single MMA per tile ----
#pragma unroll
        for (int ks = 0; ks < 4; ks++) {
            uint32_t pa[4];
            pa[0] = pack_f16x2(sc[2 * ks][0], sc[2 * ks][1]);
            pa[1] = pack_f16x2(sc[2 * ks][2], sc[2 * ks][3]);
            pa[2] = pack_f16x2(sc[2 * ks + 1][0], sc[2 * ks + 1][1]);
            pa[3] = pack_f16x2(sc[2 * ks + 1][2], sc[2 * ks + 1][3]);

            uint32_t vf4[4][4];
#pragma unroll
            for (int t = 0; t < 4; t++) {
                uint32_t addr = st + 2 * KV_TILE +
                                (ks * 16 + (mat & 1) * 8 + lr) * KV_STRIDE +
                                t * 32 + (mat >> 1) * 16;
                LDMATRIX_X4_T(vf4[t][0], vf4[t][1], vf4[t][2], vf4[t][3], addr);
            }
#pragma unroll
            for (int j = 0; j < 8; j++) {
                const int t = j >> 1, q = (j & 1) * 2;
                MMA_F16(ob[j], pa, vf4[t][q], vf4[t][q + 1]);
            }
        }
        __syncthreads();
    }
#undef FL_ISSUE

    // ---- epilogue: normalize, split bf16, write row-major att layout ----
    const float inv0 = 1.f / l0, inv1 = 1.f / l1;
    const int b = bh >> 4, h = bh & 15;
    const size_t row0 = (size_t)b * S_ + r0g;
    const size_t row1 = row0 + 8;
    uint32_t* oh32 = (uint32_t*)g_ath;
    uint32_t* ol32 = (uint32_t*)g_atl;
#pragma unroll
    for (int j = 0; j < 8; j++) {
        const int col = h * 64 + j * 8 + qc;
        uint32_t rh, rl;
        split_pack(ob[j][0] * inv0, ob[j][1] * inv0, rh, rl);
        oh32[(row0 * D_ + col) >> 1] = rh;
        ol32[(row0 * D_ + col) >> 1] = rl;
        split_pack(ob[j][2] * inv1, ob[j][3] * inv1, rh, rl);
        oh32[(row1 * D_ + col) >> 1] = rh;
        ol32[(row1 * D_ + col) >> 1] = rl;
    }
}

// ---------------------------------------------------------------------------
// Launcher. 5 launches: split, wsplit4, qkv, flash, o_proj.
// ---------------------------------------------------------------------------
extern "C" void kernel_launch(void* const* d_in, const int* in_sizes, int n_in,
                              void* d_out, int out_size)
{
    const float* x    = (const float*)d_in[0];
    const float* wq   = (const float*)d_in[1];
    const float* wk   = (const float*)d_in[2];
    const float* wv   = (const float*)d_in[3];
    const float* wo   = (const float*)d_in[4];
    const int*   tp32 = (const int*)d_in[5];
    (void)in_sizes; (void)n_in; (void)out_size;

    cudaFuncSetAttribute(hmma_qkv_kernel,
                         cudaFuncAttributeMaxDynamicSharedMemorySize, GEMM_SMEM);
    cudaFuncSetAttribute(hmma_o_kernel,
                         cudaFuncAttributeMaxDynamicSharedMemorySize, GEMM_SMEM);
    cudaFuncSetAttribute(flash_hmma_kernel,
                         cudaFuncAttributeMaxDynamicSharedMemorySize, FL_SMEM);

    void *pxh, *pxl;
    cudaGetSymbolAddress(&pxh, g_xh);
    cudaGetSymbolAddress(&pxl, g_xl);

    const int NX = M_ * D_;
    dim3 tb(32, 8), tg4(32, 32, 4);

    // 1. split x (+ RoPE tables)
    split_kernel<<<(NX + 255) / 256, 256>>>(x, (__nv_bfloat16*)pxh,
                                            (__nv_bfloat16*)pxl, NX);
    // 2. all weight transposes+splits fused
    wsplit4_kernel<<<tg4, tb>>>(wq, wk, wv, wo);

    // 3. fused QKV projections
    dim3 gqkv(D_ / 128, M_ / 128, 3);
    hmma_qkv_kernel<<<gqkv, 256, GEMM_SMEM>>>(tp32);

    // 4. flash attention — ncu capture should land here
    dim3 gf(16, B_ * H_);
    flash_hmma_kernel<<<gf, 256, FL_SMEM>>>();

    // 5. output projection (fp32 to d_out)
    dim3 gg(D_ / 128, M_ / 128);
    hmma_o_kernel<<<gg, 256, GEMM_SMEM>>>((float*)d_out);
}

// round 15
// speedup vs baseline: 1.6397x; 1.3857x over previous
#include <cuda_runtime.h>
#include <cuda_bf16.h>
#include <cuda_fp16.h>
#include <math.h>
#include <stdint.h>

// Problem constants
#define B_   4
#define S_   2048
#define D_   1024
#define H_   16
#define DK   64
#define MSEQ 2048
#define M_   (B_ * S_)   // 8192

// ---------------------------------------------------------------------------
// Scratch (__device__ globals; no allocations allowed)
// ---------------------------------------------------------------------------
__device__ float g_cos[MSEQ * (DK / 2)];
__device__ float g_sin[MSEQ * (DK / 2)];

__device__ __align__(16) __half g_xh[M_ * D_];   // x hi (fp16)
__device__ __align__(16) __half g_xl[M_ * D_];   // x lo residual (fp16)
__device__ __align__(16) __half g_ath[M_ * D_];  // attention out hi
__device__ __align__(16) __half g_atl[M_ * D_];  // attention out lo
__device__ __align__(16) __half g_qbh[M_ * D_];  // Q hi (pre-scaled)
__device__ __align__(16) __half g_qbl[M_ * D_];  // Q lo
__device__ __align__(16) __half g_kf [M_ * D_];  // K single fp16
__device__ __align__(16) __half g_vf [M_ * D_];  // V single fp16
// transposed weights, single fp16: [N=1024][K=1024]
__device__ __align__(16) __half g_wq[D_ * D_];
__device__ __align__(16) __half g_wk[D_ * D_];
__device__ __align__(16) __half g_wv[D_ * D_];
__device__ __align__(16) __half g_wo[D_ * D_];

// ---------------------------------------------------------------------------
// PTX helpers (sm_80+ only; harness compiles for plain sm_103 — no tcgen05)
// ---------------------------------------------------------------------------
__device__ __forceinline__ uint32_t smem_to_u32(const void* p) {
    uint32_t a;
    asm("{ .reg .u64 t; cvta.to.shared.u64 t, %1; cvt.u32.u64 %0, t; }"
        : "=r"(a) : "l"(p));
    return a;
}
#define CP_ASYNC16(dst_u32, src_ptr) \
    asm volatile("cp.async.cg.shared.global [%0], [%1], 16;" \
                 :: "r"(dst_u32), "l"(src_ptr))
#define CP_COMMIT() asm volatile("cp.async.commit_group;" ::: "memory")
#define CP_WAIT(n) asm volatile("cp.async.wait_group %0;" :: "n"(n) : "memory")
#define LDMATRIX_X4(r0, r1, r2, r3, addr) \
    asm volatile("ldmatrix.sync.aligned.m8n8.x4.shared.b16 {%0,%1,%2,%3}, [%4];" \
                 : "=r"(r0), "=r"(r1), "=r"(r2), "=r"(r3) : "r"(addr))
#define LDMATRIX_X4_T(r0, r1, r2, r3, addr) \
    asm volatile("ldmatrix.sync.aligned.m8n8.x4.trans.shared.b16 {%0,%1,%2,%3}, [%4];" \
                 : "=r"(r0), "=r"(r1), "=r"(r2), "=r"(r3) : "r"(addr))
#define MMA_F16(c, a, b0, b1) \
    asm volatile("mma.sync.aligned.m16n8k16.row.col.f32.f16.f16.f32 " \
                 "{%0,%1,%2,%3}, {%4,%5,%6,%7}, {%8,%9}, {%0,%1,%2,%3};" \
                 : "+f"((c)[0]), "+f"((c)[1]), "+f"((c)[2]), "+f"((c)[3]) \
                 : "r"((a)[0]), "r"((a)[1]), "r"((a)[2]), "r"((a)[3]), \
                   "r"(b0), "r"(b1))

__device__ __forceinline__ uint32_t pack_f16x2(float v0, float v1) {
    __half2 h = __floats2half2_rn(v0, v1);   // low = v0, high = v1
    return *(uint32_t*)&h;
}
// fp16 hi/lo split of a pair, packed
__device__ __forceinline__ void split_pack_h(float v0, float v1,
                                             uint32_t& rh, uint32_t& rl) {
    rh = pack_f16x2(v0, v1);
    __half2 h = *(__half2*)&rh;
    rl = pack_f16x2(v0 - __half2float(__low2half(h)),
                    v1 - __half2float(__high2half(h)));
}

// fast exp2, FFMA-only (no MUFU). |err| ~ 2e-6 relative.
__device__ __forceinline__ float exp2f_fast(float x) {
    x = fmaxf(x, -120.f);
    float z = __fadd_rn(x, 12582912.f);
    int ei = __float_as_int(z) - 0x4B400000;
    float f = x - __fadd_rn(z, -12582912.f);
    float p = 0.0013333558f;
    p = fmaf(p, f, 0.0096181291f);
    p = fmaf(p, f, 0.0555041087f);
    p = fmaf(p, f, 0.2402265070f);
    p = fmaf(p, f, 0.69314718056f);
    p = fmaf(p, f, 1.0f);
    return __int_as_float(__float_as_int(p) + (ei << 23));
}

__device__ __forceinline__ int get_pos(const int* __restrict__ tp32, int s) {
    return (tp32[1] == 0) ? tp32[2 * s] : tp32[s];
}

// ---------------------------------------------------------------------------
// split x (fp32 -> fp16 hi/lo) + RoPE tables folded in
// ---------------------------------------------------------------------------
__global__ void split_kernel(const float* __restrict__ in,
                             __half* __restrict__ hi,
                             __half* __restrict__ lo, int n)
{
    int i = blockIdx.x * blockDim.x + threadIdx.x;
    if (i < MSEQ * (DK / 2)) {
        int pos = i >> 5;
        int j   = i & 31;
        double freq = pow(10000.0, -(double)(2 * j) / (double)DK);
        double ang  = (double)pos * freq;
        g_cos[i] = (float)cos(ang);
        g_sin[i] = (float)sin(ang);
    }
    if (i < n) {
        float v = in[i];
        __half h = __float2half(v);
        hi[i] = h;
        lo[i] = __float2half(v - __half2float(h));
    }
}

// ---------------------------------------------------------------------------
// Fused weight transpose (fp32 [K][N] -> single fp16 [N][K]) for all 4.
// ---------------------------------------------------------------------------
__global__ void wsplit4_kernel(const float* __restrict__ wq,
                               const float* __restrict__ wk,
                               const float* __restrict__ wv,
                               const float* __restrict__ wo)
{
    __shared__ float t[32][33];
    const int z = blockIdx.z;
    const float* W = (z == 0) ? wq : (z == 1) ? wk : (z == 2) ? wv : wo;
    __half* th = (z == 0) ? g_wq : (z == 1) ? g_wk : (z == 2) ? g_wv : g_wo;

    int bx = blockIdx.x * 32;
    int by = blockIdx.y * 32;
    int tx = threadIdx.x, ty = threadIdx.y;
    for (int i = ty; i < 32; i += 8)
        t[i][tx] = W[(size_t)(by + i) * D_ + bx + tx];
    __syncthreads();
    for (int i = ty; i < 32; i += 8)
        th[(size_t)(bx + i) * D_ + by + tx] = __float2half(t[tx][i]);
}

// ---------------------------------------------------------------------------
// HMMA GEMM core: A = (Ah, Al) fp16 2-term, B single fp16. 2 MMAs per pair.
// 2-stage double buffer, 3 tiles per stage.
// ---------------------------------------------------------------------------
#define KCH      32
#define ROW_STR  80
#define TILE_B   (128 * ROW_STR)         // 10240
#define STAGE_B  (3 * TILE_B)            // 30720: Ah, Al, B
#define GEMM_SMEM (2 * STAGE_B)          // 61440 -> 2 CTAs/SM

__device__ __forceinline__ void gemm_core(
    const __half* __restrict__ Ah, const __half* __restrict__ Al,
    const __half* __restrict__ Bm,
    int m0, int n0, char* smem, float acc[4][4][4])
{
    const uint32_t sbase = smem_to_u32(smem);
    const int tid = threadIdx.x;
    const int w = tid >> 5;
    const int l = tid & 31;
    const int warp_m = w >> 2;
    const int warp_n = w & 3;

    const int mat = l >> 3, lr = l & 7;
    const int a_row  = warp_m * 64 + (mat & 1) * 8 + lr;
    const int a_koff = (mat >> 1) * 16;
    const int b_row  = warp_n * 32 + (mat >> 1) * 8 + lr;
    const int b_koff = (mat & 1) * 16;

    const int ld_r0 = tid >> 2;
    const int ld_c  = (tid & 3) * 16;
    const int ld_k  = (tid & 3) * 8;

#define ISSUE_STAGE(s_)                                                        \
    do {                                                                       \
        const int k0_ = (s_) * KCH;                                            \
        const uint32_t st_ = sbase + ((s_) & 1) * STAGE_B;                     \
        const __half* gsrc_[3] = {Ah, Al, Bm};                                 \
        const int grow_[3] = {m0, m0, n0};                                     \
        _Pragma("unroll")                                                      \
        for (int tI = 0; tI < 3; tI++) {                                       \
            _Pragma("unroll")                                                  \
            for (int i = 0; i < 2; i++) {                                      \
                int r_ = ld_r0 + i * 64;                                       \
                uint32_t dst_ = st_ + tI * TILE_B + r_ * ROW_STR + ld_c;       \
                const __half* src_ =                                           \
                    gsrc_[tI] + (size_t)(grow_[tI] + r_) * D_ + k0_ + ld_k;    \
                CP_ASYNC16(dst_, src_);                                        \
            }                                                                  \
        }                                                                      \
        CP_COMMIT();                                                           \
    } while (0)

    ISSUE_STAGE(0);

    for (int s = 0; s < 32; s++) {
        if (s + 1 < 32) {
            ISSUE_STAGE(s + 1);
            CP_WAIT(1);
        } else {
            CP_WAIT(0);
        }
        __syncthreads();

        const uint32_t st = sbase + (s & 1) * STAGE_B;
#pragma unroll
        for (int ks = 0; ks < 2; ks++) {
            const uint32_t kb = ks * 32;
            uint32_t ah[4][4], al[4][4], bm[2][4];
#pragma unroll
            for (int mt = 0; mt < 4; mt++) {
                uint32_t addr = st + (a_row + mt * 16) * ROW_STR + kb + a_koff;
                LDMATRIX_X4(ah[mt][0], ah[mt][1], ah[mt][2], ah[mt][3], addr);
                LDMATRIX_X4(al[mt][0], al[mt][1], al[mt][2], al[mt][3],
                            addr + TILE_B);
            }
#pragma unroll
            for (int pr = 0; pr < 2; pr++) {
                uint32_t addr = st + 2 * TILE_B +
                                (b_row + pr * 16) * ROW_STR + kb + b_koff;
                LDMATRIX_X4(bm[pr][0], bm[pr][1], bm[pr][2], bm[pr][3], addr);
            }
#pragma unroll
            for (int mt = 0; mt < 4; mt++) {
#pragma unroll
                for (int nt = 0; nt < 4; nt++) {
                    const int p = nt >> 1, q = (nt & 1) * 2;
                    MMA_F16(acc[mt][nt], ah[mt], bm[p][q], bm[p][q + 1]);
                    MMA_F16(acc[mt][nt], al[mt], bm[p][q], bm[p][q + 1]);
                }
            }
        }
        __syncthreads();
    }
#undef ISSUE_STAGE
}

#define SCL 0.18033688011112042f         // 0.125 * log2(e), folded into Q

// ---------------------------------------------------------------------------
// Fused QKV projection: z=0 Q(+rope,+SCL, fp16 hi/lo), z=1 K(+rope, fp16),
// z=2 V (fp16).
// ---------------------------------------------------------------------------
__global__ __launch_bounds__(256) void hmma_qkv_kernel(const int* __restrict__ tp32)
{
    extern __shared__ char smem[];
    const int z = blockIdx.z;
    const __half* Bm = (z == 0) ? g_wq : (z == 1) ? g_wk : g_wv;
    const int rope = (z < 2);
    const float oscale = (z == 0) ? SCL : 1.0f;

    const int n0 = blockIdx.x * 128;
    const int m0 = blockIdx.y * 128;

    float acc[4][4][4];
#pragma unroll
    for (int mt = 0; mt < 4; mt++)
#pragma unroll
        for (int nt = 0; nt < 4; nt++)
#pragma unroll
            for (int r = 0; r < 4; r++) acc[mt][nt][r] = 0.f;

    gemm_core(g_xh, g_xl, Bm, m0, n0, smem, acc);

    const int w = threadIdx.x >> 5, l = threadIdx.x & 31;
    const int warp_m = w >> 2, warp_n = w & 3;
    const int qr = l >> 2, qc = (l & 3) * 2;

    uint32_t* Oh32 = (uint32_t*)g_qbh;
    uint32_t* Ol32 = (uint32_t*)g_qbl;
    uint32_t* S32  = (uint32_t*)((z == 1) ? g_kf : g_vf);

#pragma unroll
    for (int mt = 0; mt < 4; mt++) {
        const int r0 = m0 + warp_m * 64 + mt * 16 + qr;
        const int r1 = r0 + 8;
        const float *cb0 = 0, *sb0 = 0, *cb1 = 0, *sb1 = 0;
        if (rope) {
            int p0 = get_pos(tp32, r0 & (S_ - 1));
            int p1 = get_pos(tp32, r1 & (S_ - 1));
            cb0 = g_cos + p0 * (DK / 2); sb0 = g_sin + p0 * (DK / 2);
            cb1 = g_cos + p1 * (DK / 2); sb1 = g_sin + p1 * (DK / 2);
        }
        const int b0i = r0 >> 11, s0i = r0 & (S_ - 1);
        const int b1i = r1 >> 11, s1i = r1 & (S_ - 1);
#pragma unroll
        for (int nt = 0; nt < 4; nt++) {
            const int col = n0 + warp_n * 32 + nt * 8 + qc;
            const int h = col >> 6, d = col & 63;
            float c0 = acc[mt][nt][0], c1 = acc[mt][nt][1];
            float c2 = acc[mt][nt][2], c3 = acc[mt][nt][3];
            if (rope) {
                const int pj = d >> 1;
                float cc = cb0[pj], ss = sb0[pj];
                float e = c0, o = c1;
                c0 = e * cc - o * ss; c1 = o * cc + e * ss;
                cc = cb1[pj]; ss = sb1[pj];
                e = c2; o = c3;
                c2 = e * cc - o * ss; c3 = o * cc + e * ss;
            }
            c0 *= oscale; c1 *= oscale; c2 *= oscale; c3 *= oscale;
            size_t i0 = (((size_t)(b0i * H_ + h) * S_ + s0i) * DK + d) >> 1;
            size_t i1 = (((size_t)(b1i * H_ + h) * S_ + s1i) * DK + d) >> 1;
            if (z == 0) {
                uint32_t rh, rl;
                split_pack_h(c0, c1, rh, rl);
                Oh32[i0] = rh; Ol32[i0] = rl;
                split_pack_h(c2, c3, rh, rl);
                Oh32[i1] = rh; Ol32[i1] = rl;
            } else {
                S32[i0] = pack_f16x2(c0, c1);
                S32[i1] = pack_f16x2(c2, c3);
            }
        }
    }
}

// ---------------------------------------------------------------------------
// Output projection: fp32 out = att @ Wo
// ---------------------------------------------------------------------------
__global__ __launch_bounds__(256) void hmma_o_kernel(float* __restrict__ C)
{
    extern __shared__ char smem[];
    const int n0 = blockIdx.x * 128;
    const int m0 = blockIdx.y * 128;

    float acc[4][4][4];
#pragma unroll
    for (int mt = 0; mt < 4; mt++)
#pragma unroll
        for (int nt = 0; nt < 4; nt++)
#pragma unroll
            for (int r = 0; r < 4; r++) acc[mt][nt][r] = 0.f;

    gemm_core(g_ath, g_atl, g_wo, m0, n0, smem, acc);

    const int w = threadIdx.x >> 5, l = threadIdx.x & 31;
    const int warp_m = w >> 2, warp_n = w & 3;
    const int qr = l >> 2, qc = (l & 3) * 2;
#pragma unroll
    for (int mt = 0; mt < 4; mt++) {
        const int r0 = m0 + warp_m * 64 + mt * 16 + qr;
        const int r1 = r0 + 8;
#pragma unroll
        for (int nt = 0; nt < 4; nt++) {
            const int col = n0 + warp_n * 32 + nt * 8 + qc;
            *(float2*)(C + (size_t)r0 * D_ + col) =
                make_float2(acc[mt][nt][0], acc[mt][nt][1]);
            *(float2*)(C + (size_t)r1 * D_ + col) =
                make_float2(acc[mt][nt][2], acc[mt][nt][3]);
        }
    }
}

// ---------------------------------------------------------------------------
// Flash attention, causal. Scores: Q(hi/lo fp16)·K(fp16) = 2 MMAs.
// PV: single fp16 MMA. KV stage: K + V = 2 tiles. 2-stage double buffer.
// ---------------------------------------------------------------------------
#define KV_STRIDE 144
#define KV_TILE   (64 * KV_STRIDE)       // 9216
#define FL_STAGE  (2 * KV_TILE)          // 18432: K, V
#define FL_SMEM   (2 * FL_STAGE)         // 36864

__global__ __launch_bounds__(256, 2) void flash_hmma_kernel()
{
    extern __shared__ char fs[];
    const uint32_t sbase = smem_to_u32(fs);
    const int tid = threadIdx.x;
    const int w = tid >> 5, l = tid & 31;
    const int qt = 15 - blockIdx.x;          // long blocks first
    const int bh = blockIdx.y;
    const int mat = l >> 3, lr = l & 7;
    const int qr = l >> 2, qc = (l & 3) * 2;

    const size_t bh_off = (size_t)bh * S_ * DK;
    const char* qh_g = (const char*)(g_qbh + bh_off + (size_t)qt * 128 * DK);
    const char* ql_g = (const char*)(g_qbl + bh_off + (size_t)qt * 128 * DK);
    const char* k_g  = (const char*)(g_kf + bh_off);
    const char* v_g  = (const char*)(g_vf + bh_off);

    // ---- load Q tile (128x64 hi + lo), extract frags ----
    {
#pragma unroll
        for (int t = 0; t < 2; t++) {
            const char* src = t ? ql_g : qh_g;
#pragma unroll
            for (int i = 0; i < 4; i++) {
                int p = tid + i * 256;
                int rr = p >> 3, cc = p & 7;
                CP_ASYNC16(sbase + t * 18432 + rr * KV_STRIDE + cc * 16,
                           src + ((size_t)rr * DK + cc * 8) * 2);
            }
        }
        CP_COMMIT();
        CP_WAIT(0);
        __syncthreads();
    }
    uint32_t qhf[4][4], qlf[4][4];
#pragma unroll
    for (int ks = 0; ks < 4; ks++) {
        uint32_t addr = sbase + (w * 16 + (mat & 1) * 8 + lr) * KV_STRIDE +
                        ks * 32 + (mat >> 1) * 16;
        LDMATRIX_X4(qhf[ks][0], qhf[ks][1], qhf[ks][2], qhf[ks][3], addr);
        LDMATRIX_X4(qlf[ks][0], qlf[ks][1], qlf[ks][2], qlf[ks][3], addr + 18432);
    }
    __syncthreads();

    // ---- state ----
    float m0 = -1e30f, m1 = -1e30f, l0 = 0.f, l1 = 0.f;
    float ob[8][4];
#pragma unroll
    for (int j = 0; j < 8; j++)
#pragma unroll
        for (int r = 0; r < 4; r++) ob[j][r] = 0.f;

    const int r0g = qt * 128 + w * 16 + qr;
    const int r1g = r0g + 8;
    const int ktmax = 2 * qt + 1;

#define FL_ISSUE(kt_)                                                          \
    do {                                                                       \
        const uint32_t st_ = sbase + ((kt_) & 1) * FL_STAGE;                   \
        const char* gs_[2] = {k_g, v_g};                                       \
        _Pragma("unroll")                                                      \
        for (int t = 0; t < 2; t++) {                                          \
            _Pragma("unroll")                                                  \
            for (int i = 0; i < 2; i++) {                                      \
                int p = tid + i * 256;                                         \
                int rr = p >> 3, cc = p & 7;                                   \
                CP_ASYNC16(st_ + t * KV_TILE + rr * KV_STRIDE + cc * 16,       \
                           gs_[t] + ((size_t)((kt_) * 64 + rr) * DK + cc * 8) * 2); \
            }                                                                  \
        }                                                                      \
        CP_COMMIT();                                                           \
    } while (0)

    FL_ISSUE(0);

    for (int kt = 0; kt <= ktmax; kt++) {
        if (kt + 1 <= ktmax) { FL_ISSUE(kt + 1); CP_WAIT(1); }
        else                 { CP_WAIT(0); }
        __syncthreads();

        const uint32_t st = sbase + (kt & 1) * FL_STAGE;

        // ---- scores: S = Qh*K + Ql*K (Q pre-scaled by SCL) ----
        float sc[8][4];
#pragma unroll
        for (int j = 0; j < 8; j++)
#pragma unroll
            for (int r = 0; r < 4; r++) sc[j][r] = 0.f;

#pragma unroll
        for (int ks = 0; ks < 4; ks++) {
            uint32_t kf4[4][4];
#pragma unroll
            for (int t = 0; t < 4; t++) {
                uint32_t addr = st + (t * 16 + (mat >> 1) * 8 + lr) * KV_STRIDE +
                                ks * 32 + (mat & 1) * 16;
                LDMATRIX_X4(kf4[t][0], kf4[t][1], kf4[t][2], kf4[t][3], addr);
            }
#pragma unroll
            for (int j = 0; j < 8; j++) {
                const int t = j >> 1, q = (j & 1) * 2;
                MMA_F16(sc[j], qhf[ks], kf4[t][q], kf4[t][q + 1]);
                MMA_F16(sc[j], qlf[ks], kf4[t][q], kf4[t][q + 1]);
            }
        }

        // ---- causal mask (log2 domain) ----
        if (kt >= 2 * qt) {
            const int cb = kt * 64;
#pragma unroll
            for (int j = 0; j < 8; j++) {
                int c0 = cb + j * 8 + qc, c1 = c0 + 1;
                if (c0 > r0g) sc[j][0] = -30000.f;
                if (c1 > r0g) sc[j][1] = -30000.f;
                if (c0 > r1g) sc[j][2] = -30000.f;
                if (c1 > r1g) sc[j][3] = -30000.f;
            }
        }

        // ---- online softmax (exp2 domain) ----
        float tm0 = -1e30f, tm1 = -1e30f;
#pragma unroll
        for (int j = 0; j < 8; j++) {
            tm0 = fmaxf(tm0, fmaxf(sc[j][0], sc[j][1]));
            tm1 = fmaxf(tm1, fmaxf(sc[j][2], sc[j][3]));
        }
        tm0 = fmaxf(tm0, __shfl_xor_sync(0xffffffffu, tm0, 1));
        tm0 = fmaxf(tm0, __shfl_xor_sync(0xffffffffu, tm0, 2));
        tm1 = fmaxf(tm1, __shfl_xor_sync(0xffffffffu, tm1, 1));
        tm1 = fmaxf(tm1, __shfl_xor_sync(0xffffffffu, tm1, 2));
        const float nm0 = fmaxf(m0, tm0), nm1 = fmaxf(m1, tm1);
        const float cor0 = exp2f_fast(m0 - nm0);
        const float cor1 = exp2f_fast(m1 - nm1);
        float s0 = 0.f, s1 = 0.f;
#pragma unroll
        for (int j = 0; j < 8; j++) {
            sc[j][0] = exp2f_fast(sc[j][0] - nm0);
            sc[j][1] = exp2f_fast(sc[j][1] - nm0);
            sc[j][2] = exp2f_fast(sc[j][2] - nm1);
            sc[j][3] = exp2f_fast(sc[j][3] - nm1);
            s0 += sc[j][0] + sc[j][1];
            s1 += sc[j][2] + sc[j][3];
        }
        s0 += __shfl_xor_sync(0xffffffffu, s0, 1);
        s0 += __shfl_xor_sync(0xffffffffu, s0, 2);
        s1 += __shfl_xor_sync(0xffffffffu, s1, 1);
        s1 += __shfl_xor_sync(0xffffffffu, s1, 2);
        l0 = l0 * cor0 + s0;
        l1 = l1 * cor1 + s1;
        m0 = nm0; m1 = nm1;
#pragma unroll
        for (int j = 0; j < 8; j++) {
            ob[j][0] *= cor0; ob[j][1] *= cor0;
            ob[j][2] *= cor1; ob[j][3] *= cor1;
        }

        // ---- PV: O += P (fp16) * V (fp16), single MMA per tile ----
#pragma unroll
        for (int ks = 0; ks < 4; ks++) {
            uint32_t pa[4];
            pa[0] = pack_f16x2(sc[2 * ks][0], sc[2 * ks][1]);
            pa[1] = pack_f16x2(sc[2 * ks][2], sc[2 * ks][3]);
            pa[2] = pack_f16x2(sc[2 * ks + 1][0], sc[2 * ks + 1][1]);
            pa[3] = pack_f16x2(sc[2 * ks + 1][2], sc[2 * ks + 1][3]);

            uint32_t vf4[4][4];
#pragma unroll
            for (int t = 0; t < 4; t++) {
                uint32_t addr = st + KV_TILE +
                                (ks * 16 + (mat & 1) * 8 + lr) * KV_STRIDE +
                                t * 32 + (mat >> 1) * 16;
                LDMATRIX_X4_T(vf4[t][0], vf4[t][1], vf4[t][2], vf4[t][3], addr);
            }
#pragma unroll
            for (int j = 0; j < 8; j++) {
                const int t = j >> 1, q = (j & 1) * 2;
                MMA_F16(ob[j], pa, vf4[t][q], vf4[t][q + 1]);
            }
        }
        __syncthreads();
    }
#undef FL_ISSUE

    // ---- epilogue: normalize, split fp16 hi/lo, write row-major att layout ----
    const float inv0 = 1.f / l0, inv1 = 1.f / l1;
    const int b = bh >> 4, h = bh & 15;
    const size_t row0 = (size_t)b * S_ + r0g;
    const size_t row1 = row0 + 8;
    uint32_t* oh32 = (uint32_t*)g_ath;
    uint32_t* ol32 = (uint32_t*)g_atl;
#pragma unroll
    for (int j = 0; j < 8; j++) {
        const int col = h * 64 + j * 8 + qc;
        uint32_t rh, rl;
        split_pack_h(ob[j][0] * inv0, ob[j][1] * inv0, rh, rl);
        oh32[(row0 * D_ + col) >> 1] = rh;
        ol32[(row0 * D_ + col) >> 1] = rl;
        split_pack_h(ob[j][2] * inv1, ob[j][3] * inv1, rh, rl);
        oh32[(row1 * D_ + col) >> 1] = rh;
        ol32[(row1 * D_ + col) >> 1] = rl;
    }
}

// ---------------------------------------------------------------------------
// Launcher. 5 launches: split, wsplit4, qkv, flash, o_proj.
// ---------------------------------------------------------------------------
extern "C" void kernel_launch(void* const* d_in, const int* in_sizes, int n_in,
                              void* d_out, int out_size)
{
    const float* x    = (const float*)d_in[0];
    const float* wq   = (const float*)d_in[1];
    const float* wk   = (const float*)d_in[2];
    const float* wv   = (const float*)d_in[3];
    const float* wo   = (const float*)d_in[4];
    const int*   tp32 = (const int*)d_in[5];
    (void)in_sizes; (void)n_in; (void)out_size;

    cudaFuncSetAttribute(hmma_qkv_kernel,
                         cudaFuncAttributeMaxDynamicSharedMemorySize, GEMM_SMEM);
    cudaFuncSetAttribute(hmma_o_kernel,
                         cudaFuncAttributeMaxDynamicSharedMemorySize, GEMM_SMEM);
    cudaFuncSetAttribute(flash_hmma_kernel,
                         cudaFuncAttributeMaxDynamicSharedMemorySize, FL_SMEM);

    void *pxh, *pxl;
    cudaGetSymbolAddress(&pxh, g_xh);
    cudaGetSymbolAddress(&pxl, g_xl);

    const int NX = M_ * D_;
    dim3 tb(32, 8), tg4(32, 32, 4);

    // 1. split x (+ RoPE tables)
    split_kernel<<<(NX + 255) / 256, 256>>>(x, (__half*)pxh, (__half*)pxl, NX);
    // 2. all weight transposes fused
    wsplit4_kernel<<<tg4, tb>>>(wq, wk, wv, wo);

    // 3. fused QKV projections
    dim3 gqkv(D_ / 128, M_ / 128, 3);
    hmma_qkv_kernel<<<gqkv, 256, GEMM_SMEM>>>(tp32);

    // 4. flash attention — ncu capture should land here
    dim3 gf(16, B_ * H_);
    flash_hmma_kernel<<<gf, 256, FL_SMEM>>>();

    // 5. output projection (fp32 to d_out)
    dim3 gg(D_ / 128, M_ / 128);
    hmma_o_kernel<<<gg, 256, GEMM_SMEM>>>((float*)d_out);
}

// round 16
// speedup vs baseline: 2.2000x; 1.3417x over previous
#include <cuda_runtime.h>
#include <cuda_bf16.h>
#include <cuda_fp16.h>
#include <math.h>
#include <stdint.h>

// Problem constants
#define B_   4
#define S_   2048
#define D_   1024
#define H_   16
#define DK   64
#define MSEQ 2048
#define M_   (B_ * S_)   // 8192

// ---------------------------------------------------------------------------
// Scratch (__device__ globals; no allocations allowed)
// ---------------------------------------------------------------------------
__device__ float g_cos[MSEQ * (DK / 2)];
__device__ float g_sin[MSEQ * (DK / 2)];

__device__ __align__(16) __half g_xf [M_ * D_];  // x single fp16
__device__ __align__(16) __half g_atf[M_ * D_];  // attention out single fp16
__device__ __align__(16) __half g_qbh[M_ * D_];  // Q hi (pre-scaled)
__device__ __align__(16) __half g_qbl[M_ * D_];  // Q lo
__device__ __align__(16) __half g_kf [M_ * D_];  // K single fp16
__device__ __align__(16) __half g_vf [M_ * D_];  // V single fp16
// transposed weights, single fp16: [N=1024][K=1024]
__device__ __align__(16) __half g_wq[D_ * D_];
__device__ __align__(16) __half g_wk[D_ * D_];
__device__ __align__(16) __half g_wv[D_ * D_];
__device__ __align__(16) __half g_wo[D_ * D_];

// ---------------------------------------------------------------------------
// PTX helpers (sm_80+ only; harness compiles for plain sm_103 — no tcgen05)
// ---------------------------------------------------------------------------
__device__ __forceinline__ uint32_t smem_to_u32(const void* p) {
    uint32_t a;
    asm("{ .reg .u64 t; cvta.to.shared.u64 t, %1; cvt.u32.u64 %0, t; }"
        : "=r"(a) : "l"(p));
    return a;
}
#define CP_ASYNC16(dst_u32, src_ptr) \
    asm volatile("cp.async.cg.shared.global [%0], [%1], 16;" \
                 :: "r"(dst_u32), "l"(src_ptr))
#define CP_COMMIT() asm volatile("cp.async.commit_group;" ::: "memory")
#define CP_WAIT(n) asm volatile("cp.async.wait_group %0;" :: "n"(n) : "memory")
#define LDMATRIX_X4(r0, r1, r2, r3, addr) \
    asm volatile("ldmatrix.sync.aligned.m8n8.x4.shared.b16 {%0,%1,%2,%3}, [%4];" \
                 : "=r"(r0), "=r"(r1), "=r"(r2), "=r"(r3) : "r"(addr))
#define LDMATRIX_X4_T(r0, r1, r2, r3, addr) \
    asm volatile("ldmatrix.sync.aligned.m8n8.x4.trans.shared.b16 {%0,%1,%2,%3}, [%4];" \
                 : "=r"(r0), "=r"(r1), "=r"(r2), "=r"(r3) : "r"(addr))
#define MMA_F16(c, a, b0, b1) \
    asm volatile("mma.sync.aligned.m16n8k16.row.col.f32.f16.f16.f32 " \
                 "{%0,%1,%2,%3}, {%4,%5,%6,%7}, {%8,%9}, {%0,%1,%2,%3};" \
                 : "+f"((c)[0]), "+f"((c)[1]), "+f"((c)[2]), "+f"((c)[3]) \
                 : "r"((a)[0]), "r"((a)[1]), "r"((a)[2]), "r"((a)[3]), \
                   "r"(b0), "r"(b1))

__device__ __forceinline__ uint32_t pack_f16x2(float v0, float v1) {
    __half2 h = __floats2half2_rn(v0, v1);   // low = v0, high = v1
    return *(uint32_t*)&h;
}
// fp16 hi/lo split of a pair, packed
__device__ __forceinline__ void split_pack_h(float v0, float v1,
                                             uint32_t& rh, uint32_t& rl) {
    rh = pack_f16x2(v0, v1);
    __half2 h = *(__half2*)&rh;
    rl = pack_f16x2(v0 - __half2float(__low2half(h)),
                    v1 - __half2float(__high2half(h)));
}

// fast exp2, FFMA-only (no MUFU). |err| ~ 2e-6 relative.
__device__ __forceinline__ float exp2f_fast(float x) {
    x = fmaxf(x, -120.f);
    float z = __fadd_rn(x, 12582912.f);
    int ei = __float_as_int(z) - 0x4B400000;
    float f = x - __fadd_rn(z, -12582912.f);
    float p = 0.0013333558f;
    p = fmaf(p, f, 0.0096181291f);
    p = fmaf(p, f, 0.0555041087f);
    p = fmaf(p, f, 0.2402265070f);
    p = fmaf(p, f, 0.69314718056f);
    p = fmaf(p, f, 1.0f);
    return __int_as_float(__float_as_int(p) + (ei << 23));
}

__device__ __forceinline__ int get_pos(const int* __restrict__ tp32, int s) {
    return (tp32[1] == 0) ? tp32[2 * s] : tp32[s];
}

// ---------------------------------------------------------------------------
// x -> single fp16 + RoPE tables folded in
// ---------------------------------------------------------------------------
__global__ void split_kernel(const float* __restrict__ in,
                             __half* __restrict__ hi, int n)
{
    int i = blockIdx.x * blockDim.x + threadIdx.x;
    if (i < MSEQ * (DK / 2)) {
        int pos = i >> 5;
        int j   = i & 31;
        double freq = pow(10000.0, -(double)(2 * j) / (double)DK);
        double ang  = (double)pos * freq;
        g_cos[i] = (float)cos(ang);
        g_sin[i] = (float)sin(ang);
    }
    if (i < n) hi[i] = __float2half(in[i]);
}

// ---------------------------------------------------------------------------
// Fused weight transpose (fp32 [K][N] -> single fp16 [N][K]) for all 4.
// ---------------------------------------------------------------------------
__global__ void wsplit4_kernel(const float* __restrict__ wq,
                               const float* __restrict__ wk,
                               const float* __restrict__ wv,
                               const float* __restrict__ wo)
{
    __shared__ float t[32][33];
    const int z = blockIdx.z;
    const float* W = (z == 0) ? wq : (z == 1) ? wk : (z == 2) ? wv : wo;
    __half* th = (z == 0) ? g_wq : (z == 1) ? g_wk : (z == 2) ? g_wv : g_wo;

    int bx = blockIdx.x * 32;
    int by = blockIdx.y * 32;
    int tx = threadIdx.x, ty = threadIdx.y;
    for (int i = ty; i < 32; i += 8)
        t[i][tx] = W[(size_t)(by + i) * D_ + bx + tx];
    __syncthreads();
    for (int i = ty; i < 32; i += 8)
        th[(size_t)(bx + i) * D_ + by + tx] = __float2half(t[tx][i]);
}

// ---------------------------------------------------------------------------
// HMMA GEMM core: single fp16 A x single fp16 B, 1 MMA per (mt,nt).
// 2-stage double buffer, 2 tiles per stage.
// ---------------------------------------------------------------------------
#define KCH      32
#define ROW_STR  80
#define TILE_B   (128 * ROW_STR)         // 10240
#define STAGE_B  (2 * TILE_B)            // 20480: A, B
#define GEMM_SMEM (2 * STAGE_B)          // 40960

__device__ __forceinline__ void gemm_core(
    const __half* __restrict__ Am, const __half* __restrict__ Bm,
    int m0, int n0, char* smem, float acc[4][4][4])
{
    const uint32_t sbase = smem_to_u32(smem);
    const int tid = threadIdx.x;
    const int w = tid >> 5;
    const int l = tid & 31;
    const int warp_m = w >> 2;
    const int warp_n = w & 3;

    const int mat = l >> 3, lr = l & 7;
    const int a_row  = warp_m * 64 + (mat & 1) * 8 + lr;
    const int a_koff = (mat >> 1) * 16;
    const int b_row  = warp_n * 32 + (mat >> 1) * 8 + lr;
    const int b_koff = (mat & 1) * 16;

    const int ld_r0 = tid >> 2;
    const int ld_c  = (tid & 3) * 16;
    const int ld_k  = (tid & 3) * 8;

#define ISSUE_STAGE(s_)                                                        \
    do {                                                                       \
        const int k0_ = (s_) * KCH;                                            \
        const uint32_t st_ = sbase + ((s_) & 1) * STAGE_B;                     \
        const __half* gsrc_[2] = {Am, Bm};                                     \
        const int grow_[2] = {m0, n0};                                         \
        _Pragma("unroll")                                                      \
        for (int tI = 0; tI < 2; tI++) {                                       \
            _Pragma("unroll")                                                  \
            for (int i = 0; i < 2; i++) {                                      \
                int r_ = ld_r0 + i * 64;                                       \
                uint32_t dst_ = st_ + tI * TILE_B + r_ * ROW_STR + ld_c;       \
                const __half* src_ =                                           \
                    gsrc_[tI] + (size_t)(grow_[tI] + r_) * D_ + k0_ + ld_k;    \
                CP_ASYNC16(dst_, src_);                                        \
            }                                                                  \
        }                                                                      \
        CP_COMMIT();                                                           \
    } while (0)

    ISSUE_STAGE(0);

    for (int s = 0; s < 32; s++) {
        if (s + 1 < 32) {
            ISSUE_STAGE(s + 1);
            CP_WAIT(1);
        } else {
            CP_WAIT(0);
        }
        __syncthreads();

        const uint32_t st = sbase + (s & 1) * STAGE_B;
#pragma unroll
        for (int ks = 0; ks < 2; ks++) {
            const uint32_t kb = ks * 32;
            uint32_t am[4][4], bm[2][4];
#pragma unroll
            for (int mt = 0; mt < 4; mt++) {
                uint32_t addr = st + (a_row + mt * 16) * ROW_STR + kb + a_koff;
                LDMATRIX_X4(am[mt][0], am[mt][1], am[mt][2], am[mt][3], addr);
            }
#pragma unroll
            for (int pr = 0; pr < 2; pr++) {
                uint32_t addr = st + TILE_B +
                                (b_row + pr * 16) * ROW_STR + kb + b_koff;
                LDMATRIX_X4(bm[pr][0], bm[pr][1], bm[pr][2], bm[pr][3], addr);
            }
#pragma unroll
            for (int mt = 0; mt < 4; mt++) {
#pragma unroll
                for (int nt = 0; nt < 4; nt++) {
                    const int p = nt >> 1, q = (nt & 1) * 2;
                    MMA_F16(acc[mt][nt], am[mt], bm[p][q], bm[p][q + 1]);
                }
            }
        }
        __syncthreads();
    }
#undef ISSUE_STAGE
}

#define SCL 0.18033688011112042f         // 0.125 * log2(e), folded into Q

// ---------------------------------------------------------------------------
// Fused QKV projection: z=0 Q(+rope,+SCL, fp16 hi/lo out), z=1 K(+rope, fp16),
// z=2 V (fp16).
// ---------------------------------------------------------------------------
__global__ __launch_bounds__(256) void hmma_qkv_kernel(const int* __restrict__ tp32)
{
    extern __shared__ char smem[];
    const int z = blockIdx.z;
    const __half* Bm = (z == 0) ? g_wq : (z == 1) ? g_wk : g_wv;
    const int rope = (z < 2);
    const float oscale = (z == 0) ? SCL : 1.0f;

    const int n0 = blockIdx.x * 128;
    const int m0 = blockIdx.y * 128;

    float acc[4][4][4];
#pragma unroll
    for (int mt = 0; mt < 4; mt++)
#pragma unroll
        for (int nt = 0; nt < 4; nt++)
#pragma unroll
            for (int r = 0; r < 4; r++) acc[mt][nt][r] = 0.f;

    gemm_core(g_xf, Bm, m0, n0, smem, acc);

    const int w = threadIdx.x >> 5, l = threadIdx.x & 31;
    const int warp_m = w >> 2, warp_n = w & 3;
    const int qr = l >> 2, qc = (l & 3) * 2;

    uint32_t* Oh32 = (uint32_t*)g_qbh;
    uint32_t* Ol32 = (uint32_t*)g_qbl;
    uint32_t* S32  = (uint32_t*)((z == 1) ? g_kf : g_vf);

#pragma unroll
    for (int mt = 0; mt < 4; mt++) {
        const int r0 = m0 + warp_m * 64 + mt * 16 + qr;
        const int r1 = r0 + 8;
        const float *cb0 = 0, *sb0 = 0, *cb1 = 0, *sb1 = 0;
        if (rope) {
            int p0 = get_pos(tp32, r0 & (S_ - 1));
            int p1 = get_pos(tp32, r1 & (S_ - 1));
            cb0 = g_cos + p0 * (DK / 2); sb0 = g_sin + p0 * (DK / 2);
            cb1 = g_cos + p1 * (DK / 2); sb1 = g_sin + p1 * (DK / 2);
        }
        const int b0i = r0 >> 11, s0i = r0 & (S_ - 1);
        const int b1i = r1 >> 11, s1i = r1 & (S_ - 1);
#pragma unroll
        for (int nt = 0; nt < 4; nt++) {
            const int col = n0 + warp_n * 32 + nt * 8 + qc;
            const int h = col >> 6, d = col & 63;
            float c0 = acc[mt][nt][0], c1 = acc[mt][nt][1];
            float c2 = acc[mt][nt][2], c3 = acc[mt][nt][3];
            if (rope) {
                const int pj = d >> 1;
                float cc = cb0[pj], ss = sb0[pj];
                float e = c0, o = c1;
                c0 = e * cc - o * ss; c1 = o * cc + e * ss;
                cc = cb1[pj]; ss = sb1[pj];
                e = c2; o = c3;
                c2 = e * cc - o * ss; c3 = o * cc + e * ss;
            }
            c0 *= oscale; c1 *= oscale; c2 *= oscale; c3 *= oscale;
            size_t i0 = (((size_t)(b0i * H_ + h) * S_ + s0i) * DK + d) >> 1;
            size_t i1 = (((size_t)(b1i * H_ + h) * S_ + s1i) * DK + d) >> 1;
            if (z == 0) {
                uint32_t rh, rl;
                split_pack_h(c0, c1, rh, rl);
                Oh32[i0] = rh; Ol32[i0] = rl;
                split_pack_h(c2, c3, rh, rl);
                Oh32[i1] = rh; Ol32[i1] = rl;
            } else {
                S32[i0] = pack_f16x2(c0, c1);
                S32[i1] = pack_f16x2(c2, c3);
            }
        }
    }
}

// ---------------------------------------------------------------------------
// Output projection: fp32 out = att @ Wo
// ---------------------------------------------------------------------------
__global__ __launch_bounds__(256) void hmma_o_kernel(float* __restrict__ C)
{
    extern __shared__ char smem[];
    const int n0 = blockIdx.x * 128;
    const int m0 = blockIdx.y * 128;

    float acc[4][4][4];
#pragma unroll
    for (int mt = 0; mt < 4; mt++)
#pragma unroll
        for (int nt = 0; nt < 4; nt++)
#pragma unroll
            for (int r = 0; r < 4; r++) acc[mt][nt][r] = 0.f;

    gemm_core(g_atf, g_wo, m0, n0, smem, acc);

    const int w = threadIdx.x >> 5, l = threadIdx.x & 31;
    const int warp_m = w >> 2, warp_n = w & 3;
    const int qr = l >> 2, qc = (l & 3) * 2;
#pragma unroll
    for (int mt = 0; mt < 4; mt++) {
        const int r0 = m0 + warp_m * 64 + mt * 16 + qr;
        const int r1 = r0 + 8;
#pragma unroll
        for (int nt = 0; nt < 4; nt++) {
            const int col = n0 + warp_n * 32 + nt * 8 + qc;
            *(float2*)(C + (size_t)r0 * D_ + col) =
                make_float2(acc[mt][nt][0], acc[mt][nt][1]);
            *(float2*)(C + (size_t)r1 * D_ + col) =
                make_float2(acc[mt][nt][2], acc[mt][nt][3]);
        }
    }
}

// ---------------------------------------------------------------------------
// Flash attention, causal. Scores: Q(hi/lo fp16)·K(fp16) = 2 MMAs.
// PV: single fp16 MMA. KV stage: K + V = 2 tiles. 2-stage double buffer.
// ---------------------------------------------------------------------------
#define KV_STRIDE 144
#define KV_TILE   (64 * KV_STRIDE)       // 9216
#define FL_STAGE  (2 * KV_TILE)          // 18432: K, V
#define FL_SMEM   (2 * FL_STAGE)         // 36864

__global__ __launch_bounds__(256, 2) void flash_hmma_kernel()
{
    extern __shared__ char fs[];
    const uint32_t sbase = smem_to_u32(fs);
    const int tid = threadIdx.x;
    const int w = tid >> 5, l = tid & 31;
    const int qt = 15 - blockIdx.x;          // long blocks first
    const int bh = blockIdx.y;
    const int mat = l >> 3, lr = l & 7;
    const int qr = l >> 2, qc = (l & 3) * 2;

    const size_t bh_off = (size_t)bh * S_ * DK;
    const char* qh_g = (const char*)(g_qbh + bh_off + (size_t)qt * 128 * DK);
    const char* ql_g = (const char*)(g_qbl + bh_off + (size_t)qt * 128 * DK);
    const char* k_g  = (const char*)(g_kf + bh_off);
    const char* v_g  = (const char*)(g_vf + bh_off);

    // ---- load Q tile (128x64 hi + lo), extract frags ----
    {
#pragma unroll
        for (int t = 0; t < 2; t++) {
            const char* src = t ? ql_g : qh_g;
#pragma unroll
            for (int i = 0; i < 4; i++) {
                int p = tid + i * 256;
                int rr = p >> 3, cc = p & 7;
                CP_ASYNC16(sbase + t * 18432 + rr * KV_STRIDE + cc * 16,
                           src + ((size_t)rr * DK + cc * 8) * 2);
            }
        }
        CP_COMMIT();
        CP_WAIT(0);
        __syncthreads();
    }
    uint32_t qhf[4][4], qlf[4][4];
#pragma unroll
    for (int ks = 0; ks < 4; ks++) {
        uint32_t addr = sbase + (w * 16 + (mat & 1) * 8 + lr) * KV_STRIDE +
                        ks * 32 + (mat >> 1) * 16;
        LDMATRIX_X4(qhf[ks][0], qhf[ks][1], qhf[ks][2], qhf[ks][3], addr);
        LDMATRIX_X4(qlf[ks][0], qlf[ks][1], qlf[ks][2], qlf[ks][3], addr + 18432);
    }
    __syncthreads();

    // ---- state ----
    float m0 = -1e30f, m1 = -1e30f, l0 = 0.f, l1 = 0.f;
    float ob[8][4];
#pragma unroll
    for (int j = 0; j < 8; j++)
#pragma unroll
        for (int r = 0; r < 4; r++) ob[j][r] = 0.f;

    const int r0g = qt * 128 + w * 16 + qr;
    const int r1g = r0g + 8;
    const int ktmax = 2 * qt + 1;

#define FL_ISSUE(kt_)                                                          \
    do {                                                                       \
        const uint32_t st_ = sbase + ((kt_) & 1) * FL_STAGE;                   \
        const char* gs_[2] = {k_g, v_g};                                       \
        _Pragma("unroll")                                                      \
        for (int t = 0; t < 2; t++) {                                          \
            _Pragma("unroll")                                                  \
            for (int i = 0; i < 2; i++) {                                      \
                int p = tid + i * 256;                                         \
                int rr = p >> 3, cc = p & 7;                                   \
                CP_ASYNC16(st_ + t * KV_TILE + rr * KV_STRIDE + cc * 16,       \
                           gs_[t] + ((size_t)((kt_) * 64 + rr) * DK + cc * 8) * 2); \
            }                                                                  \
        }                                                                      \
        CP_COMMIT();                                                           \
    } while (0)

    FL_ISSUE(0);

    for (int kt = 0; kt <= ktmax; kt++) {
        if (kt + 1 <= ktmax) { FL_ISSUE(kt + 1); CP_WAIT(1); }
        else                 { CP_WAIT(0); }
        __syncthreads();

        const uint32_t st = sbase + (kt & 1) * FL_STAGE;

        // ---- scores: S = Qh*K + Ql*K (Q pre-scaled by SCL) ----
        float sc[8][4];
#pragma unroll
        for (int j = 0; j < 8; j++)
#pragma unroll
            for (int r = 0; r < 4; r++) sc[j][r] = 0.f;

#pragma unroll
        for (int ks = 0; ks < 4; ks++) {
            uint32_t kf4[4][4];
#pragma unroll
            for (int t = 0; t < 4; t++) {
                uint32_t addr = st + (t * 16 + (mat >> 1) * 8 + lr) * KV_STRIDE +
                                ks * 32 + (mat & 1) * 16;
                LDMATRIX_X4(kf4[t][0], kf4[t][1], kf4[t][2], kf4[t][3], addr);
            }
#pragma unroll
            for (int j = 0; j < 8; j++) {
                const int t = j >> 1, q = (j & 1) * 2;
                MMA_F16(sc[j], qhf[ks], kf4[t][q], kf4[t][q + 1]);
                MMA_F16(sc[j], qlf[ks], kf4[t][q], kf4[t][q + 1]);
            }
        }

        // ---- causal mask (log2 domain) ----
        if (kt >= 2 * qt) {
            const int cb = kt * 64;
#pragma unroll
            for (int j = 0; j < 8; j++) {
                int c0 = cb + j * 8 + qc, c1 = c0 + 1;
                if (c0 > r0g) sc[j][0] = -30000.f;
                if (c1 > r0g) sc[j][1] = -30000.f;
                if (c0 > r1g) sc[j][2] = -30000.f;
                if (c1 > r1g) sc[j][3] = -30000.f;
            }
        }

        // ---- online softmax (exp2 domain) ----
        float tm0 = -1e30f, tm1 = -1e30f;
#pragma unroll
        for (int j = 0; j < 8; j++) {
            tm0 = fmaxf(tm0, fmaxf(sc[j][0], sc[j][1]));
            tm1 = fmaxf(tm1, fmaxf(sc[j][2], sc[j][3]));
        }
        tm0 = fmaxf(tm0, __shfl_xor_sync(0xffffffffu, tm0, 1));
        tm0 = fmaxf(tm0, __shfl_xor_sync(0xffffffffu, tm0, 2));
        tm1 = fmaxf(tm1, __shfl_xor_sync(0xffffffffu, tm1, 1));
        tm1 = fmaxf(tm1, __shfl_xor_sync(0xffffffffu, tm1, 2));
        const float nm0 = fmaxf(m0, tm0), nm1 = fmaxf(m1, tm1);
        const float cor0 = exp2f_fast(m0 - nm0);
        const float cor1 = exp2f_fast(m1 - nm1);
        float s0 = 0.f, s1 = 0.f;
#pragma unroll
        for (int j = 0; j < 8; j++) {
            sc[j][0] = exp2f_fast(sc[j][0] - nm0);
            sc[j][1] = exp2f_fast(sc[j][1] - nm0);
            sc[j][2] = exp2f_fast(sc[j][2] - nm1);
            sc[j][3] = exp2f_fast(sc[j][3] - nm1);
            s0 += sc[j][0] + sc[j][1];
            s1 += sc[j][2] + sc[j][3];
        }
        s0 += __shfl_xor_sync(0xffffffffu, s0, 1);
        s0 += __shfl_xor_sync(0xffffffffu, s0, 2);
        s1 += __shfl_xor_sync(0xffffffffu, s1, 1);
        s1 += __shfl_xor_sync(0xffffffffu, s1, 2);
        l0 = l0 * cor0 + s0;
        l1 = l1 * cor1 + s1;
        m0 = nm0; m1 = nm1;
#pragma unroll
        for (int j = 0; j < 8; j++) {
            ob[j][0] *= cor0; ob[j][1] *= cor0;
            ob[j][2] *= cor1; ob[j][3] *= cor1;
        }

        // ---- PV: O += P (fp16) * V (fp16), single MMA per tile ----
#pragma unroll
        for (int ks = 0; ks < 4; ks++) {
            uint32_t pa[4];
            pa[0] = pack_f16x2(sc[2 * ks][0], sc[2 * ks][1]);
            pa[1] = pack_f16x2(sc[2 * ks][2], sc[2 * ks][3]);
            pa[2] = pack_f16x2(sc[2 * ks + 1][0], sc[2 * ks + 1][1]);
            pa[3] = pack_f16x2(sc[2 * ks + 1][2], sc[2 * ks + 1][3]);

            uint32_t vf4[4][4];
#pragma unroll
            for (int t = 0; t < 4; t++) {
                uint32_t addr = st + KV_TILE +
                                (ks * 16 + (mat & 1) * 8 + lr) * KV_STRIDE +
                                t * 32 + (mat >> 1) * 16;
                LDMATRIX_X4_T(vf4[t][0], vf4[t][1], vf4[t][2], vf4[t][3], addr);
            }
#pragma unroll
            for (int j = 0; j < 8; j++) {
                const int t = j >> 1, q = (j & 1) * 2;
                MMA_F16(ob[j], pa, vf4[t][q], vf4[t][q + 1]);
            }
        }
        __syncthreads();
    }
#undef FL_ISSUE

    // ---- epilogue: normalize, single fp16, write row-major att layout ----
    const float inv0 = 1.f / l0, inv1 = 1.f / l1;
    const int b = bh >> 4, h = bh & 15;
    const size_t row0 = (size_t)b * S_ + r0g;
    const size_t row1 = row0 + 8;
    uint32_t* o32 = (uint32_t*)g_atf;
#pragma unroll
    for (int j = 0; j < 8; j++) {
        const int col = h * 64 + j * 8 + qc;
        o32[(row0 * D_ + col) >> 1] = pack_f16x2(ob[j][0] * inv0, ob[j][1] * inv0);
        o32[(row1 * D_ + col) >> 1] = pack_f16x2(ob[j][2] * inv1, ob[j][3] * inv1);
    }
}

// ---------------------------------------------------------------------------
// Launcher. 5 launches: split, wsplit4, qkv, flash, o_proj.
// ---------------------------------------------------------------------------
extern "C" void kernel_launch(void* const* d_in, const int* in_sizes, int n_in,
                              void* d_out, int out_size)
{
    const float* x    = (const float*)d_in[0];
    const float* wq   = (const float*)d_in[1];
    const float* wk   = (const float*)d_in[2];
    const float* wv   = (const float*)d_in[3];
    const float* wo   = (const float*)d_in[4];
    const int*   tp32 = (const int*)d_in[5];
    (void)in_sizes; (void)n_in; (void)out_size;

    cudaFuncSetAttribute(hmma_qkv_kernel,
                         cudaFuncAttributeMaxDynamicSharedMemorySize, GEMM_SMEM);
    cudaFuncSetAttribute(hmma_o_kernel,
                         cudaFuncAttributeMaxDynamicSharedMemorySize, GEMM_SMEM);
    cudaFuncSetAttribute(flash_hmma_kernel,
                         cudaFuncAttributeMaxDynamicSharedMemorySize, FL_SMEM);

    void *pxf;
    cudaGetSymbolAddress(&pxf, g_xf);

    const int NX = M_ * D_;
    dim3 tb(32, 8), tg4(32, 32, 4);

    // 1. x -> fp16 (+ RoPE tables)
    split_kernel<<<(NX + 255) / 256, 256>>>(x, (__half*)pxf, NX);
    // 2. all weight transposes fused
    wsplit4_kernel<<<tg4, tb>>>(wq, wk, wv, wo);

    // 3. fused QKV projections
    dim3 gqkv(D_ / 128, M_ / 128, 3);
    hmma_qkv_kernel<<<gqkv, 256, GEMM_SMEM>>>(tp32);

    // 4. flash attention — ncu capture lands here
    dim3 gf(16, B_ * H_);
    flash_hmma_kernel<<<gf, 256, FL_SMEM>>>();

    // 5. output projection (fp32 to d_out)
    dim3 gg(D_ / 128, M_ / 128);
    hmma_o_kernel<<<gg, 256, GEMM_SMEM>>>((float*)d_out);
}

// round 17
// speedup vs baseline: 2.3672x; 1.0760x over previous
#include <cuda_runtime.h>
#include <cuda_bf16.h>
#include <cuda_fp16.h>
#include <math.h>
#include <stdint.h>

// Problem constants
#define B_   4
#define S_   2048
#define D_   1024
#define H_   16
#define DK   64
#define MSEQ 2048
#define M_   (B_ * S_)   // 8192

// ---------------------------------------------------------------------------
// Scratch (__device__ globals; no allocations allowed)
// ---------------------------------------------------------------------------
__device__ float g_cos[MSEQ * (DK / 2)];
__device__ float g_sin[MSEQ * (DK / 2)];

__device__ __align__(16) __half g_xf [M_ * D_];  // x single fp16
__device__ __align__(16) __half g_atf[M_ * D_];  // attention out single fp16
__device__ __align__(16) __half g_qf [M_ * D_];  // Q single fp16 (pre-scaled)
__device__ __align__(16) __half g_kf [M_ * D_];  // K single fp16
__device__ __align__(16) __half g_vf [M_ * D_];  // V single fp16
// transposed weights, single fp16: [N=1024][K=1024]
__device__ __align__(16) __half g_wq[D_ * D_];
__device__ __align__(16) __half g_wk[D_ * D_];
__device__ __align__(16) __half g_wv[D_ * D_];
__device__ __align__(16) __half g_wo[D_ * D_];

// ---------------------------------------------------------------------------
// PTX helpers (sm_80+ only; harness compiles for plain sm_103 — no tcgen05)
// ---------------------------------------------------------------------------
__device__ __forceinline__ uint32_t smem_to_u32(const void* p) {
    uint32_t a;
    asm("{ .reg .u64 t; cvta.to.shared.u64 t, %1; cvt.u32.u64 %0, t; }"
        : "=r"(a) : "l"(p));
    return a;
}
#define CP_ASYNC16(dst_u32, src_ptr) \
    asm volatile("cp.async.cg.shared.global [%0], [%1], 16;" \
                 :: "r"(dst_u32), "l"(src_ptr))
#define CP_COMMIT() asm volatile("cp.async.commit_group;" ::: "memory")
#define CP_WAIT(n) asm volatile("cp.async.wait_group %0;" :: "n"(n) : "memory")
#define LDMATRIX_X4(r0, r1, r2, r3, addr) \
    asm volatile("ldmatrix.sync.aligned.m8n8.x4.shared.b16 {%0,%1,%2,%3}, [%4];" \
                 : "=r"(r0), "=r"(r1), "=r"(r2), "=r"(r3) : "r"(addr))
#define LDMATRIX_X4_T(r0, r1, r2, r3, addr) \
    asm volatile("ldmatrix.sync.aligned.m8n8.x4.trans.shared.b16 {%0,%1,%2,%3}, [%4];" \
                 : "=r"(r0), "=r"(r1), "=r"(r2), "=r"(r3) : "r"(addr))
#define MMA_F16(c, a, b0, b1) \
    asm volatile("mma.sync.aligned.m16n8k16.row.col.f32.f16.f16.f32 " \
                 "{%0,%1,%2,%3}, {%4,%5,%6,%7}, {%8,%9}, {%0,%1,%2,%3};" \
                 : "+f"((c)[0]), "+f"((c)[1]), "+f"((c)[2]), "+f"((c)[3]) \
                 : "r"((a)[0]), "r"((a)[1]), "r"((a)[2]), "r"((a)[3]), \
                   "r"(b0), "r"(b1))

__device__ __forceinline__ uint32_t pack_f16x2(float v0, float v1) {
    __half2 h = __floats2half2_rn(v0, v1);   // low = v0, high = v1
    return *(uint32_t*)&h;
}

// fast exp2, FFMA-only (no MUFU). |err| ~ 2e-6 relative.
__device__ __forceinline__ float exp2f_fast(float x) {
    x = fmaxf(x, -120.f);
    float z = __fadd_rn(x, 12582912.f);
    int ei = __float_as_int(z) - 0x4B400000;
    float f = x - __fadd_rn(z, -12582912.f);
    float p = 0.0013333558f;
    p = fmaf(p, f, 0.0096181291f);
    p = fmaf(p, f, 0.0555041087f);
    p = fmaf(p, f, 0.2402265070f);
    p = fmaf(p, f, 0.69314718056f);
    p = fmaf(p, f, 1.0f);
    return __int_as_float(__float_as_int(p) + (ei << 23));
}

__device__ __forceinline__ int get_pos(const int* __restrict__ tp32, int s) {
    return (tp32[1] == 0) ? tp32[2 * s] : tp32[s];
}

// ---------------------------------------------------------------------------
// x -> single fp16 + RoPE tables folded in
// ---------------------------------------------------------------------------
__global__ void split_kernel(const float* __restrict__ in,
                             __half* __restrict__ hi, int n)
{
    int i = blockIdx.x * blockDim.x + threadIdx.x;
    if (i < MSEQ * (DK / 2)) {
        int pos = i >> 5;
        int j   = i & 31;
        double freq = pow(10000.0, -(double)(2 * j) / (double)DK);
        double ang  = (double)pos * freq;
        g_cos[i] = (float)cos(ang);
        g_sin[i] = (float)sin(ang);
    }
    if (i < n) hi[i] = __float2half(in[i]);
}

// ---------------------------------------------------------------------------
// Fused weight transpose (fp32 [K][N] -> single fp16 [N][K]) for all 4.
// ---------------------------------------------------------------------------
__global__ void wsplit4_kernel(const float* __restrict__ wq,
                               const float* __restrict__ wk,
                               const float* __restrict__ wv,
                               const float* __restrict__ wo)
{
    __shared__ float t[32][33];
    const int z = blockIdx.z;
    const float* W = (z == 0) ? wq : (z == 1) ? wk : (z == 2) ? wv : wo;
    __half* th = (z == 0) ? g_wq : (z == 1) ? g_wk : (z == 2) ? g_wv : g_wo;

    int bx = blockIdx.x * 32;
    int by = blockIdx.y * 32;
    int tx = threadIdx.x, ty = threadIdx.y;
    for (int i = ty; i < 32; i += 8)
        t[i][tx] = W[(size_t)(by + i) * D_ + bx + tx];
    __syncthreads();
    for (int i = ty; i < 32; i += 8)
        th[(size_t)(bx + i) * D_ + by + tx] = __float2half(t[tx][i]);
}

// ---------------------------------------------------------------------------
// HMMA GEMM core (R16-proven): single fp16 A x single fp16 B, 1 MMA per tile.
// 2-stage double buffer, 2 tiles per stage.
// ---------------------------------------------------------------------------
#define KCH      32
#define ROW_STR  80
#define TILE_B   (128 * ROW_STR)         // 10240
#define STAGE_B  (2 * TILE_B)            // 20480: A, B
#define GEMM_SMEM (2 * STAGE_B)          // 40960

__device__ __forceinline__ void gemm_core(
    const __half* __restrict__ Am, const __half* __restrict__ Bm,
    int m0, int n0, char* smem, float acc[4][4][4])
{
    const uint32_t sbase = smem_to_u32(smem);
    const int tid = threadIdx.x;
    const int w = tid >> 5;
    const int l = tid & 31;
    const int warp_m = w >> 2;
    const int warp_n = w & 3;

    const int mat = l >> 3, lr = l & 7;
    const int a_row  = warp_m * 64 + (mat & 1) * 8 + lr;
    const int a_koff = (mat >> 1) * 16;
    const int b_row  = warp_n * 32 + (mat >> 1) * 8 + lr;
    const int b_koff = (mat & 1) * 16;

    const int ld_r0 = tid >> 2;
    const int ld_c  = (tid & 3) * 16;
    const int ld_k  = (tid & 3) * 8;

#define ISSUE_STAGE(s_)                                                        \
    do {                                                                       \
        const int k0_ = (s_) * KCH;                                            \
        const uint32_t st_ = sbase + ((s_) & 1) * STAGE_B;                     \
        const __half* gsrc_[2] = {Am, Bm};                                     \
        const int grow_[2] = {m0, n0};                                         \
        _Pragma("unroll")                                                      \
        for (int tI = 0; tI < 2; tI++) {                                       \
            _Pragma("unroll")                                                  \
            for (int i = 0; i < 2; i++) {                                      \
                int r_ = ld_r0 + i * 64;                                       \
                uint32_t dst_ = st_ + tI * TILE_B + r_ * ROW_STR + ld_c;       \
                const __half* src_ =                                           \
                    gsrc_[tI] + (size_t)(grow_[tI] + r_) * D_ + k0_ + ld_k;    \
                CP_ASYNC16(dst_, src_);                                        \
            }                                                                  \
        }                                                                      \
        CP_COMMIT();                                                           \
    } while (0)

    ISSUE_STAGE(0);

    for (int s = 0; s < 32; s++) {
        if (s + 1 < 32) {
            ISSUE_STAGE(s + 1);
            CP_WAIT(1);
        } else {
            CP_WAIT(0);
        }
        __syncthreads();

        const uint32_t st = sbase + (s & 1) * STAGE_B;
#pragma unroll
        for (int ks = 0; ks < 2; ks++) {
            const uint32_t kb = ks * 32;
            uint32_t am[4][4], bm[2][4];
#pragma unroll
            for (int mt = 0; mt < 4; mt++) {
                uint32_t addr = st + (a_row + mt * 16) * ROW_STR + kb + a_koff;
                LDMATRIX_X4(am[mt][0], am[mt][1], am[mt][2], am[mt][3], addr);
            }
#pragma unroll
            for (int pr = 0; pr < 2; pr++) {
                uint32_t addr = st + TILE_B +
                                (b_row + pr * 16) * ROW_STR + kb + b_koff;
                LDMATRIX_X4(bm[pr][0], bm[pr][1], bm[pr][2], bm[pr][3], addr);
            }
#pragma unroll
            for (int mt = 0; mt < 4; mt++) {
#pragma unroll
                for (int nt = 0; nt < 4; nt++) {
                    const int p = nt >> 1, q = (nt & 1) * 2;
                    MMA_F16(acc[mt][nt], am[mt], bm[p][q], bm[p][q + 1]);
                }
            }
        }
        __syncthreads();
    }
#undef ISSUE_STAGE
}

#define SCL 0.18033688011112042f         // 0.125 * log2(e), folded into Q

// ---------------------------------------------------------------------------
// Fused QKV projection: z=0 Q(+rope,+SCL), z=1 K(+rope), z=2 V.
// All outputs single fp16 in [b][h][s][d] layout.
// ---------------------------------------------------------------------------
__global__ __launch_bounds__(256) void hmma_qkv_kernel(const int* __restrict__ tp32)
{
    extern __shared__ char smem[];
    const int z = blockIdx.z;
    const __half* Bm = (z == 0) ? g_wq : (z == 1) ? g_wk : g_wv;
    const int rope = (z < 2);
    const float oscale = (z == 0) ? SCL : 1.0f;

    const int n0 = blockIdx.x * 128;
    const int m0 = blockIdx.y * 128;

    float acc[4][4][4];
#pragma unroll
    for (int mt = 0; mt < 4; mt++)
#pragma unroll
        for (int nt = 0; nt < 4; nt++)
#pragma unroll
            for (int r = 0; r < 4; r++) acc[mt][nt][r] = 0.f;

    gemm_core(g_xf, Bm, m0, n0, smem, acc);

    const int w = threadIdx.x >> 5, l = threadIdx.x & 31;
    const int warp_m = w >> 2, warp_n = w & 3;
    const int qr = l >> 2, qc = (l & 3) * 2;

    uint32_t* S32 = (uint32_t*)((z == 0) ? g_qf : (z == 1) ? g_kf : g_vf);

#pragma unroll
    for (int mt = 0; mt < 4; mt++) {
        const int r0 = m0 + warp_m * 64 + mt * 16 + qr;
        const int r1 = r0 + 8;
        const float *cb0 = 0, *sb0 = 0, *cb1 = 0, *sb1 = 0;
        if (rope) {
            int p0 = get_pos(tp32, r0 & (S_ - 1));
            int p1 = get_pos(tp32, r1 & (S_ - 1));
            cb0 = g_cos + p0 * (DK / 2); sb0 = g_sin + p0 * (DK / 2);
            cb1 = g_cos + p1 * (DK / 2); sb1 = g_sin + p1 * (DK / 2);
        }
        const int b0i = r0 >> 11, s0i = r0 & (S_ - 1);
        const int b1i = r1 >> 11, s1i = r1 & (S_ - 1);
#pragma unroll
        for (int nt = 0; nt < 4; nt++) {
            const int col = n0 + warp_n * 32 + nt * 8 + qc;
            const int h = col >> 6, d = col & 63;
            float c0 = acc[mt][nt][0], c1 = acc[mt][nt][1];
            float c2 = acc[mt][nt][2], c3 = acc[mt][nt][3];
            if (rope) {
                const int pj = d >> 1;
                float cc = cb0[pj], ss = sb0[pj];
                float e = c0, o = c1;
                c0 = e * cc - o * ss; c1 = o * cc + e * ss;
                cc = cb1[pj]; ss = sb1[pj];
                e = c2; o = c3;
                c2 = e * cc - o * ss; c3 = o * cc + e * ss;
            }
            c0 *= oscale; c1 *= oscale; c2 *= oscale; c3 *= oscale;
            size_t i0 = (((size_t)(b0i * H_ + h) * S_ + s0i) * DK + d) >> 1;
            size_t i1 = (((size_t)(b1i * H_ + h) * S_ + s1i) * DK + d) >> 1;
            S32[i0] = pack_f16x2(c0, c1);
            S32[i1] = pack_f16x2(c2, c3);
        }
    }
}

// ---------------------------------------------------------------------------
// Output projection: fp32 out = att @ Wo
// ---------------------------------------------------------------------------
__global__ __launch_bounds__(256) void hmma_o_kernel(float* __restrict__ C)
{
    extern __shared__ char smem[];
    const int n0 = blockIdx.x * 128;
    const int m0 = blockIdx.y * 128;

    float acc[4][4][4];
#pragma unroll
    for (int mt = 0; mt < 4; mt++)
#pragma unroll
        for (int nt = 0; nt < 4; nt++)
#pragma unroll
            for (int r = 0; r < 4; r++) acc[mt][nt][r] = 0.f;

    gemm_core(g_atf, g_wo, m0, n0, smem, acc);

    const int w = threadIdx.x >> 5, l = threadIdx.x & 31;
    const int warp_m = w >> 2, warp_n = w & 3;
    const int qr = l >> 2, qc = (l & 3) * 2;
#pragma unroll
    for (int mt = 0; mt < 4; mt++) {
        const int r0 = m0 + warp_m * 64 + mt * 16 + qr;
        const int r1 = r0 + 8;
#pragma unroll
        for (int nt = 0; nt < 4; nt++) {
            const int col = n0 + warp_n * 32 + nt * 8 + qc;
            *(float2*)(C + (size_t)r0 * D_ + col) =
                make_float2(acc[mt][nt][0], acc[mt][nt][1]);
            *(float2*)(C + (size_t)r1 * D_ + col) =
                make_float2(acc[mt][nt][2], acc[mt][nt][3]);
        }
    }
}

// ---------------------------------------------------------------------------
// Flash attention, causal. Scores: Q(fp16)·K(fp16) = 1 MMA. PV: 1 fp16 MMA.
// 3-stage KV ring (K+V = 18KB/stage), prefetch depth 2, ONE sync per iter.
// ---------------------------------------------------------------------------
#define KV_STRIDE 144
#define KV_TILE   (64 * KV_STRIDE)       // 9216
#define FL_STAGE  (2 * KV_TILE)          // 18432: K, V
#define FL_SMEM   (3 * FL_STAGE)         // 55296 -> 2 CTAs/SM

__global__ __launch_bounds__(256, 2) void flash_hmma_kernel()
{
    extern __shared__ char fs[];
    const uint32_t sbase = smem_to_u32(fs);
    const int tid = threadIdx.x;
    const int w = tid >> 5, l = tid & 31;
    const int qt = 15 - blockIdx.x;          // long blocks first
    const int bh = blockIdx.y;
    const int mat = l >> 3, lr = l & 7;
    const int qr = l >> 2, qc = (l & 3) * 2;

    const size_t bh_off = (size_t)bh * S_ * DK;
    const char* q_g = (const char*)(g_qf + bh_off + (size_t)qt * 128 * DK);
    const char* k_g = (const char*)(g_kf + bh_off);
    const char* v_g = (const char*)(g_vf + bh_off);

    // ---- load Q tile (128x64) into stage-0 area, extract frags ----
    {
#pragma unroll
        for (int i = 0; i < 4; i++) {
            int p = tid + i * 256;
            int rr = p >> 3, cc = p & 7;
            CP_ASYNC16(sbase + rr * KV_STRIDE + cc * 16,
                       q_g + ((size_t)rr * DK + cc * 8) * 2);
        }
        CP_COMMIT();
        CP_WAIT(0);
        __syncthreads();
    }
    uint32_t qf[4][4];
#pragma unroll
    for (int ks = 0; ks < 4; ks++) {
        uint32_t addr = sbase + (w * 16 + (mat & 1) * 8 + lr) * KV_STRIDE +
                        ks * 32 + (mat >> 1) * 16;
        LDMATRIX_X4(qf[ks][0], qf[ks][1], qf[ks][2], qf[ks][3], addr);
    }
    __syncthreads();   // all Q frags extracted before stage-0 reuse

    // ---- state ----
    float m0 = -1e30f, m1 = -1e30f, l0 = 0.f, l1 = 0.f;
    float ob[8][4];
#pragma unroll
    for (int j = 0; j < 8; j++)
#pragma unroll
        for (int r = 0; r < 4; r++) ob[j][r] = 0.f;

    const int r0g = qt * 128 + w * 16 + qr;
    const int r1g = r0g + 8;
    const int ktmax = 2 * qt + 1;

#define FL_ISSUE(kt_)                                                          \
    do {                                                                       \
        const uint32_t st_ = sbase + ((kt_) % 3) * FL_STAGE;                   \
        const char* gs_[2] = {k_g, v_g};                                       \
        _Pragma("unroll")                                                      \
        for (int t = 0; t < 2; t++) {                                          \
            _Pragma("unroll")                                                  \
            for (int i = 0; i < 2; i++) {                                      \
                int p = tid + i * 256;                                         \
                int rr = p >> 3, cc = p & 7;                                   \
                CP_ASYNC16(st_ + t * KV_TILE + rr * KV_STRIDE + cc * 16,       \
                           gs_[t] + ((size_t)((kt_) * 64 + rr) * DK + cc * 8) * 2); \
            }                                                                  \
        }                                                                      \
        CP_COMMIT();                                                           \
    } while (0)

    FL_ISSUE(0);
    if (1 <= ktmax) FL_ISSUE(1);

    for (int kt = 0; kt <= ktmax; kt++) {
        if (kt + 1 <= ktmax) CP_WAIT(1);
        else                 CP_WAIT(0);
        __syncthreads();     // single barrier per iteration
        if (kt + 2 <= ktmax) FL_ISSUE(kt + 2);

        const uint32_t st = sbase + (kt % 3) * FL_STAGE;

        // ---- scores: S = Q*K (Q pre-scaled by SCL) ----
        float sc[8][4];
#pragma unroll
        for (int j = 0; j < 8; j++)
#pragma unroll
            for (int r = 0; r < 4; r++) sc[j][r] = 0.f;

#pragma unroll
        for (int ks = 0; ks < 4; ks++) {
            uint32_t kf4[4][4];
#pragma unroll
            for (int t = 0; t < 4; t++) {
                uint32_t addr = st + (t * 16 + (mat >> 1) * 8 + lr) * KV_STRIDE +
                                ks * 32 + (mat & 1) * 16;
                LDMATRIX_X4(kf4[t][0], kf4[t][1], kf4[t][2], kf4[t][3], addr);
            }
#pragma unroll
            for (int j = 0; j < 8; j++) {
                const int t = j >> 1, q = (j & 1) * 2;
                MMA_F16(sc[j], qf[ks], kf4[t][q], kf4[t][q + 1]);
            }
        }

        // ---- causal mask (log2 domain) ----
        if (kt >= 2 * qt) {
            const int cb = kt * 64;
#pragma unroll
            for (int j = 0; j < 8; j++) {
                int c0 = cb + j * 8 + qc, c1 = c0 + 1;
                if (c0 > r0g) sc[j][0] = -30000.f;
                if (c1 > r0g) sc[j][1] = -30000.f;
                if (c0 > r1g) sc[j][2] = -30000.f;
                if (c1 > r1g) sc[j][3] = -30000.f;
            }
        }

        // ---- online softmax (exp2 domain) ----
        float tm0 = -1e30f, tm1 = -1e30f;
#pragma unroll
        for (int j = 0; j < 8; j++) {
            tm0 = fmaxf(tm0, fmaxf(sc[j][0], sc[j][1]));
            tm1 = fmaxf(tm1, fmaxf(sc[j][2], sc[j][3]));
        }
        tm0 = fmaxf(tm0, __shfl_xor_sync(0xffffffffu, tm0, 1));
        tm0 = fmaxf(tm0, __shfl_xor_sync(0xffffffffu, tm0, 2));
        tm1 = fmaxf(tm1, __shfl_xor_sync(0xffffffffu, tm1, 1));
        tm1 = fmaxf(tm1, __shfl_xor_sync(0xffffffffu, tm1, 2));
        const float nm0 = fmaxf(m0, tm0), nm1 = fmaxf(m1, tm1);
        const float cor0 = exp2f_fast(m0 - nm0);
        const float cor1 = exp2f_fast(m1 - nm1);
        float s0 = 0.f, s1 = 0.f;
#pragma unroll
        for (int j = 0; j < 8; j++) {
            sc[j][0] = exp2f_fast(sc[j][0] - nm0);
            sc[j][1] = exp2f_fast(sc[j][1] - nm0);
            sc[j][2] = exp2f_fast(sc[j][2] - nm1);
            sc[j][3] = exp2f_fast(sc[j][3] - nm1);
            s0 += sc[j][0] + sc[j][1];
            s1 += sc[j][2] + sc[j][3];
        }
        s0 += __shfl_xor_sync(0xffffffffu, s0, 1);
        s0 += __shfl_xor_sync(0xffffffffu, s0, 2);
        s1 += __shfl_xor_sync(0xffffffffu, s1, 1);
        s1 += __shfl_xor_sync(0xffffffffu, s1, 2);
        l0 = l0 * cor0 + s0;
        l1 = l1 * cor1 + s1;
        m0 = nm0; m1 = nm1;
#pragma unroll
        for (int j = 0; j < 8; j++) {
            ob[j][0] *= cor0; ob[j][1] *= cor0;
            ob[j][2] *= cor1; ob[j][3] *= cor1;
        }

        // ---- PV: O += P (fp16) * V (fp16), single MMA per tile ----
#pragma unroll
        for (int ks = 0; ks < 4; ks++) {
            uint32_t pa[4];
            pa[0] = pack_f16x2(sc[2 * ks][0], sc[2 * ks][1]);
            pa[1] = pack_f16x2(sc[2 * ks][2], sc[2 * ks][3]);
            pa[2] = pack_f16x2(sc[2 * ks + 1][0], sc[2 * ks + 1][1]);
            pa[3] = pack_f16x2(sc[2 * ks + 1][2], sc[2 * ks + 1][3]);

            uint32_t vf4[4][4];
#pragma unroll
            for (int t = 0; t < 4; t++) {
                uint32_t addr = st + KV_TILE +
                                (ks * 16 + (mat & 1) * 8 + lr) * KV_STRIDE +
                                t * 32 + (mat >> 1) * 16;
                LDMATRIX_X4_T(vf4[t][0], vf4[t][1], vf4[t][2], vf4[t][3], addr);
            }
#pragma unroll
            for (int j = 0; j < 8; j++) {
                const int t = j >> 1, q = (j & 1) * 2;
                MMA_F16(ob[j], pa, vf4[t][q], vf4[t][q + 1]);
            }
        }
        // no end-of-loop barrier: next iter's single barrier covers reuse
    }
#undef FL_ISSUE

    // ---- epilogue: normalize, single fp16, write row-major att layout ----
    const float inv0 = 1.f / l0, inv1 = 1.f / l1;
    const int b = bh >> 4, h = bh & 15;
    const size_t row0 = (size_t)b * S_ + r0g;
    const size_t row1 = row0 + 8;
    uint32_t* o32 = (uint32_t*)g_atf;
#pragma unroll
    for (int j = 0; j < 8; j++) {
        const int col = h * 64 + j * 8 + qc;
        o32[(row0 * D_ + col) >> 1] = pack_f16x2(ob[j][0] * inv0, ob[j][1] * inv0);
        o32[(row1 * D_ + col) >> 1] = pack_f16x2(ob[j][2] * inv1, ob[j][3] * inv1);
    }
}

// ---------------------------------------------------------------------------
// Launcher. 5 launches: split, wsplit4, qkv, flash, o_proj.
// ---------------------------------------------------------------------------
extern "C" void kernel_launch(void* const* d_in, const int* in_sizes, int n_in,
                              void* d_out, int out_size)
{
    const float* x    = (const float*)d_in[0];
    const float* wq   = (const float*)d_in[1];
    const float* wk   = (const float*)d_in[2];
    const float* wv   = (const float*)d_in[3];
    const float* wo   = (const float*)d_in[4];
    const int*   tp32 = (const int*)d_in[5];
    (void)in_sizes; (void)n_in; (void)out_size;

    cudaFuncSetAttribute(hmma_qkv_kernel,
                         cudaFuncAttributeMaxDynamicSharedMemorySize, GEMM_SMEM);
    cudaFuncSetAttribute(hmma_o_kernel,
                         cudaFuncAttributeMaxDynamicSharedMemorySize, GEMM_SMEM);
    cudaFuncSetAttribute(flash_hmma_kernel,
                         cudaFuncAttributeMaxDynamicSharedMemorySize, FL_SMEM);

    void *pxf;
    cudaGetSymbolAddress(&pxf, g_xf);

    const int NX = M_ * D_;
    dim3 tb(32, 8), tg4(32, 32, 4);

    // 1. x -> fp16 (+ RoPE tables)
    split_kernel<<<(NX + 255) / 256, 256>>>(x, (__half*)pxf, NX);
    // 2. all weight transposes fused
    wsplit4_kernel<<<tg4, tb>>>(wq, wk, wv, wo);

    // 3. fused QKV projections
    dim3 gqkv(D_ / 128, M_ / 128, 3);
    hmma_qkv_kernel<<<gqkv, 256, GEMM_SMEM>>>(tp32);

    // 4. flash attention — ncu capture lands here
    dim3 gf(16, B_ * H_);
    flash_hmma_kernel<<<gf, 256, FL_SMEM>>>();

    // 5. output projection (fp32 to d_out)
    dim3 gg(D_ / 128, M_ / 128);
    hmma_o_kernel<<<gg, 256, GEMM_SMEM>>>((float*)d_out);
}